// round 1
// baseline (speedup 1.0000x reference)
#include <cuda_runtime.h>
#include <math.h>

#define BB  4
#define AA  256
#define NN  64
#define NCB 128
#define NF  128
#define NSB 50

// ---------------- scratch (no allocs allowed) ----------------
__device__ float d_y[BB*AA*NF];            // xi @ in2f_W        (512 KB)
__device__ float d_vij[(size_t)BB*AA*NN*NCB]; // pair output     (32 MB)
__device__ float d_Vik[BB*AA*NCB*3];       // env reduction      (1.5 MB)

__device__ __forceinline__ float sspf(float x) {
    // softplus(x) - ln(2), numerically stable
    float sp = (x > 15.f) ? x : log1pf(expf(x));
    return sp - 0.69314718055994531f;
}

// ---------------- kernel 1: per-atom embedding ----------------
__global__ void k_embed(const float* __restrict__ xi, const float* __restrict__ W) {
    int row = blockIdx.x;           // b*A + a
    int c   = threadIdx.x;          // 0..127
    __shared__ float sx[NF];
    sx[c] = xi[(size_t)row*NF + c];
    __syncthreads();
    float acc = 0.f;
    #pragma unroll 8
    for (int k = 0; k < NF; k++)
        acc = fmaf(sx[k], W[k*NF + c], acc);
    d_y[(size_t)row*NF + c] = acc;
}

// ---------------- shared-mem GEMM tile: [64 x K] @ [K x 128] ----------------
// MODE 0: ssp(x + b)   MODE 1: (x + b) * rowScale[r]   MODE 2: x + b
template<int K, int LDA, int MODE>
__device__ __forceinline__ void block_gemm(const float* __restrict__ sA,
                                           const float* __restrict__ sW,
                                           const float* __restrict__ gBias,
                                           float* __restrict__ sOut,
                                           const float* __restrict__ rowScale) {
    int tid = threadIdx.x;
    int r0 = (tid >> 5) * 8;        // 8 warps -> 64 rows
    int c0 = (tid & 31) * 4;        // 32 lanes -> 128 cols (float4)
    float acc[8][4];
    #pragma unroll
    for (int i = 0; i < 8; i++)
        #pragma unroll
        for (int j = 0; j < 4; j++) acc[i][j] = 0.f;

    #pragma unroll 2
    for (int k = 0; k < K; k++) {
        float4 wv = *reinterpret_cast<const float4*>(sW + k*NF + c0);
        #pragma unroll
        for (int i = 0; i < 8; i++) {
            float av = sA[(r0 + i)*LDA + k];   // warp-broadcast
            acc[i][0] = fmaf(av, wv.x, acc[i][0]);
            acc[i][1] = fmaf(av, wv.y, acc[i][1]);
            acc[i][2] = fmaf(av, wv.z, acc[i][2]);
            acc[i][3] = fmaf(av, wv.w, acc[i][3]);
        }
    }
    float4 bb = *reinterpret_cast<const float4*>(gBias + c0);
    #pragma unroll
    for (int i = 0; i < 8; i++) {
        float4 o;
        o.x = acc[i][0] + bb.x; o.y = acc[i][1] + bb.y;
        o.z = acc[i][2] + bb.z; o.w = acc[i][3] + bb.w;
        if (MODE == 0) { o.x = sspf(o.x); o.y = sspf(o.y); o.z = sspf(o.z); o.w = sspf(o.w); }
        if (MODE == 1) { float s = rowScale[r0 + i]; o.x *= s; o.y *= s; o.z *= s; o.w *= s; }
        *reinterpret_cast<float4*>(sOut + (r0 + i)*NF + c0) = o;
    }
}

__device__ __forceinline__ void load_w(const float* __restrict__ g, float* __restrict__ sW,
                                       int nfloats) {
    for (int i = threadIdx.x * 4; i < nfloats; i += 256 * 4)
        *reinterpret_cast<float4*>(sW + i) = *reinterpret_cast<const float4*>(g + i);
}

// ---------------- kernel 2: fused interaction per (b,a) ----------------
__global__ void __launch_bounds__(256, 1) k_main(
    const float* __restrict__ r_ij, const float* __restrict__ cos_ij,
    const float* __restrict__ f_ij, const float* __restrict__ nmask,
    const float* __restrict__ fW1, const float* __restrict__ fb1,
    const float* __restrict__ fW2, const float* __restrict__ fb2,
    const float* __restrict__ f2oW, const float* __restrict__ f2ob,
    const float* __restrict__ aW1, const float* __restrict__ ab1,
    const float* __restrict__ aW2, const float* __restrict__ ab2,
    const float* __restrict__ pW1, const float* __restrict__ pb1,
    const float* __restrict__ pW2, const float* __restrict__ pb2,
    const float* __restrict__ eW1, const float* __restrict__ eb1,
    const float* __restrict__ eW2, const float* __restrict__ eb2,
    const int* __restrict__ neighbors, float* __restrict__ out_vi)
{
    extern __shared__ float smem[];
    float* sF = smem;            // 64*50  = 3200 (pad to 3264)
    float* sA = sF + 3264;       // 64*128
    float* sB = sA + 8192;       // 64*128
    float* sV = sB + 8192;       // 64*128
    float* sW = sV + 8192;       // 128*128
    __shared__ float sMask[NN], sCut[NN], sCos[NN*3], vsum[NF], hid[NF];
    __shared__ int   sNbr[NN];

    int ba = blockIdx.x;
    int b  = ba >> 8;
    int tid = threadIdx.x;

    const float* fg = f_ij + (size_t)ba * NN * NSB;
    for (int i = tid; i < NN*NSB; i += 256) sF[i] = fg[i];
    if (tid < NN) {
        float r = r_ij[ba*NN + tid];
        sCut[tid]  = (r < 5.f) ? 0.5f * (cosf(r * 0.62831853071795864f) + 1.f) : 0.f;
        sMask[tid] = nmask[ba*NN + tid];
        sNbr[tid]  = neighbors[ba*NN + tid];
    }
    if (tid < NN*3) sCos[tid] = cos_ij[(size_t)ba*NN*3 + tid];
    __syncthreads();

    // --- filter net: h1 = ssp(f @ W1 + b1) ; Wf = (h1 @ W2 + b2) * C ---
    load_w(fW1, sW, NSB*NF); __syncthreads();
    block_gemm<NSB, NSB, 0>(sF, sW, fb1, sA, nullptr); __syncthreads();
    load_w(fW2, sW, NF*NF); __syncthreads();
    block_gemm<NF, NF, 1>(sA, sW, fb2, sB, sCut); __syncthreads();   // sB = Wf

    // --- gather yj and multiply elementwise ---
    for (int i = tid; i < NN*NF; i += 256) {
        int n = i >> 7, c = i & 127;
        sA[i] = d_y[(size_t)((b << 8) + sNbr[n]) * NF + c] * sB[i];
    }
    __syncthreads();

    // --- v = ssp((yj*Wf) @ f2out + b) ---
    load_w(f2oW, sW, NF*NF); __syncthreads();
    block_gemm<NF, NF, 0>(sA, sW, f2ob, sV, nullptr); __syncthreads();

    // --- pair MLP -> vij -> global scratch ---
    load_w(pW1, sW, NF*NF); __syncthreads();
    block_gemm<NF, NF, 0>(sV, sW, pb1, sA, nullptr); __syncthreads();
    load_w(pW2, sW, NF*NF); __syncthreads();
    block_gemm<NF, NF, 2>(sA, sW, pb2, sB, nullptr); __syncthreads();
    {
        float* vg = d_vij + (size_t)ba * NN * NCB;
        for (int i = tid; i < NN*NCB; i += 256) vg[i] = sB[i];
    }

    // --- env MLP -> vik ---
    load_w(eW1, sW, NF*NF); __syncthreads();
    block_gemm<NF, NF, 0>(sV, sW, eb1, sA, nullptr); __syncthreads();
    load_w(eW2, sW, NF*NF); __syncthreads();
    block_gemm<NF, NF, 2>(sA, sW, eb2, sB, nullptr); __syncthreads();  // sB = vik

    // --- Vik[c,d] = sum_n vik[n,c]*cos[n,d]*mask[n] ---
    for (int e = tid; e < NCB*3; e += 256) {
        int c = e / 3, d = e - c*3;
        float s = 0.f;
        for (int n = 0; n < NN; n++)
            s = fmaf(sB[n*NF + c], sCos[n*3 + d] * sMask[n], s);
        d_Vik[(size_t)ba * (NCB*3) + e] = s;
    }
    // --- vsum[c] = sum_n v[n,c]*mask[n] ---
    if (tid < NF) {
        float s = 0.f;
        for (int n = 0; n < NN; n++)
            s = fmaf(sV[n*NF + tid], sMask[n], s);
        vsum[tid] = s;
    }
    __syncthreads();
    // --- vi = mlp2(vsum, atom) ---
    if (tid < NF) {
        float h = ab1[tid];
        for (int k = 0; k < NF; k++) h = fmaf(vsum[k], aW1[k*NF + tid], h);
        hid[tid] = sspf(h);
    }
    __syncthreads();
    if (tid < NF) {
        float o = ab2[tid];
        for (int k = 0; k < NF; k++) o = fmaf(hid[k], aW2[k*NF + tid], o);
        out_vi[(size_t)ba * NF + tid] = o;
    }
}

// ---------------- kernel 3: assemble V ----------------
__global__ void k_assemble(const float* __restrict__ cos_ij,
                           const int* __restrict__ neighbors,
                           float* __restrict__ outV) {
    int idx = blockIdx.x;            // (b,a,n) flat, 65536
    int tid = threadIdx.x;           // channel c, 0..127
    int ba  = idx >> 6;
    int b   = idx >> 14;
    int nb  = neighbors[idx];
    float c0 = cos_ij[(size_t)idx*3 + 0];
    float c1 = cos_ij[(size_t)idx*3 + 1];
    float c2 = cos_ij[(size_t)idx*3 + 2];
    float vij = d_vij[(size_t)idx * NCB + tid];
    const float* vl = d_Vik + (size_t)ba * (NCB*3) + tid*3;
    const float* vn = d_Vik + ((size_t)(b*AA + nb)) * (NCB*3) + tid*3;
    float* o = outV + (size_t)idx * (NCB*3) + tid*3;
    o[0] = fmaf(vij, c0, vl[0] + vn[0]);
    o[1] = fmaf(vij, c1, vl[1] + vn[1]);
    o[2] = fmaf(vij, c2, vl[2] + vn[2]);
}

// ---------------- launch ----------------
extern "C" void kernel_launch(void* const* d_in, const int* in_sizes, int n_in,
                              void* d_out, int out_size) {
    const float* xi       = (const float*)d_in[0];
    const float* r_ij     = (const float*)d_in[1];
    const float* cos_ij   = (const float*)d_in[2];
    const float* f_ij     = (const float*)d_in[3];
    const float* nmask    = (const float*)d_in[4];
    const float* fW1      = (const float*)d_in[5];
    const float* fb1      = (const float*)d_in[6];
    const float* fW2      = (const float*)d_in[7];
    const float* fb2      = (const float*)d_in[8];
    const float* in2f_W   = (const float*)d_in[9];
    const float* f2oW     = (const float*)d_in[10];
    const float* f2ob     = (const float*)d_in[11];
    const float* aW1      = (const float*)d_in[12];
    const float* ab1      = (const float*)d_in[13];
    const float* aW2      = (const float*)d_in[14];
    const float* ab2      = (const float*)d_in[15];
    const float* pW1      = (const float*)d_in[16];
    const float* pb1      = (const float*)d_in[17];
    const float* pW2      = (const float*)d_in[18];
    const float* pb2      = (const float*)d_in[19];
    const float* eW1      = (const float*)d_in[20];
    const float* eb1      = (const float*)d_in[21];
    const float* eW2      = (const float*)d_in[22];
    const float* eb2      = (const float*)d_in[23];
    const int*   neighbors= (const int*)d_in[24];

    float* out = (float*)d_out;
    float* out_vi = out;                         // [B,A,NCB]
    float* out_V  = out + (size_t)BB*AA*NCB;     // [B,A,N,NCB,3]

    static const size_t SMEM_BYTES = (3264 + 3*8192 + 16384) * sizeof(float); // ~173 KB
    cudaFuncSetAttribute(k_main, cudaFuncAttributeMaxDynamicSharedMemorySize,
                         (int)SMEM_BYTES);

    k_embed<<<BB*AA, NF>>>(xi, in2f_W);
    k_main<<<BB*AA, 256, SMEM_BYTES>>>(
        r_ij, cos_ij, f_ij, nmask,
        fW1, fb1, fW2, fb2, f2oW, f2ob,
        aW1, ab1, aW2, ab2, pW1, pb1, pW2, pb2,
        eW1, eb1, eW2, eb2, neighbors, out_vi);
    k_assemble<<<BB*AA*NN, NF>>>(cos_ij, neighbors, out_V);
}

// round 2
// speedup vs baseline: 1.1273x; 1.1273x over previous
#include <cuda_runtime.h>
#include <math.h>

#define BB  4
#define AA  256
#define NN  64
#define NCB 128
#define NF  128
#define NSB 50

typedef unsigned long long ull;

// ---------------- scratch (no allocs allowed) ----------------
__device__ float d_y[BB*AA*NF];               // xi @ in2f_W     (512 KB)
__device__ float d_vij[(size_t)BB*AA*NN*NCB]; // pair output     (32 MB)
__device__ float d_Vik[BB*AA*NCB*3];          // env reduction   (1.5 MB)

__device__ __forceinline__ float sspf(float x) {
    float sp = (x > 15.f) ? x : log1pf(expf(x));
    return sp - 0.69314718055994531f;
}

__device__ __forceinline__ void cp_async16(float* smem_ptr, const float* gptr) {
    unsigned s = (unsigned)__cvta_generic_to_shared(smem_ptr);
    asm volatile("cp.async.cg.shared.global [%0], [%1], 16;" :: "r"(s), "l"(gptr));
}

// ---------------- kernel 1: per-atom embedding ----------------
__global__ void k_embed(const float* __restrict__ xi, const float* __restrict__ W) {
    int row = blockIdx.x;
    int c   = threadIdx.x;
    __shared__ float sx[NF];
    sx[c] = xi[(size_t)row*NF + c];
    __syncthreads();
    float acc = 0.f;
    #pragma unroll 8
    for (int k = 0; k < NF; k++)
        acc = fmaf(sx[k], W[k*NF + c], acc);
    d_y[(size_t)row*NF + c] = acc;
}

// ---------------- transposed-activation packed GEMM ----------------
// Computes Out[64 x 128] = A[64 x K] @ W[K x 128]  (+bias, +activation)
// A stored transposed in smem: sAT[k*66 + r].  Output also transposed:
// sOutT[c*66 + r].  Accumulators packed over row pairs (fma.rn.f32x2).
// MODE 0: ssp(x+b)   MODE 1: (x+b)*rowScale[r]   MODE 2: x+b
// If nextW != nullptr, prefetch it into sWbuf (cp.async) overlapped with
// the epilogue.
template<int K, int MODE>
__device__ __forceinline__ void gemm_t(
    const float* __restrict__ sAT, const float* __restrict__ sW,
    const float* __restrict__ gBias, float* __restrict__ sOutT,
    const float* __restrict__ sCut,
    const float* __restrict__ nextW, int nextWn, float* __restrict__ sWbuf)
{
    const int tid  = threadIdx.x;
    const int lane = tid & 31;
    const int r0   = (tid >> 5) * 8;          // 8 warps x 8 rows

    ull acc[4][4];
    #pragma unroll
    for (int p = 0; p < 4; p++)
        #pragma unroll
        for (int j = 0; j < 4; j++) acc[p][j] = 0ull;

    const float* aB = sAT + r0;
    const float* wB = sW + lane;

    #pragma unroll 2
    for (int k = 0; k < K; k++) {
        ull a[4];
        #pragma unroll
        for (int p = 0; p < 4; p++)
            a[p] = *reinterpret_cast<const ull*>(aB + k*66 + 2*p);
        ull wd[4];
        #pragma unroll
        for (int j = 0; j < 4; j++) {
            float w = wB[k*NF + 32*j];
            asm("mov.b64 %0, {%1, %1};" : "=l"(wd[j]) : "f"(w));
        }
        #pragma unroll
        for (int p = 0; p < 4; p++)
            #pragma unroll
            for (int j = 0; j < 4; j++)
                asm("fma.rn.f32x2 %0, %1, %2, %0;"
                    : "+l"(acc[p][j]) : "l"(a[p]), "l"(wd[j]));
    }

    __syncthreads();   // all warps done reading sW / sAT

    if (nextW) {
        for (int i = tid*4; i < nextWn; i += 1024)
            cp_async16(sWbuf + i, nextW + i);
        asm volatile("cp.async.commit_group;" ::: "memory");
    }

    #pragma unroll
    for (int j = 0; j < 4; j++) {
        int c = lane + 32*j;
        float bb = gBias[c];
        #pragma unroll
        for (int p = 0; p < 4; p++) {
            float lo, hi;
            asm("mov.b64 {%0, %1}, %2;" : "=f"(lo), "=f"(hi) : "l"(acc[p][j]));
            lo += bb; hi += bb;
            if (MODE == 0) { lo = sspf(lo); hi = sspf(hi); }
            if (MODE == 1) { lo *= sCut[r0 + 2*p]; hi *= sCut[r0 + 2*p + 1]; }
            ull pk;
            asm("mov.b64 %0, {%1, %2};" : "=l"(pk) : "f"(lo), "f"(hi));
            *reinterpret_cast<ull*>(sOutT + c*66 + r0 + 2*p) = pk;
        }
    }

    if (nextW) asm volatile("cp.async.wait_group 0;" ::: "memory");
    __syncthreads();
}

// smem float offsets
#define OFF_FT 0
#define OFF_A  3328
#define OFF_B  (3328 + 8448)
#define OFF_V  (3328 + 2*8448)
#define OFF_W  (3328 + 3*8448)
#define SMEM_FLOATS (3328 + 3*8448 + 16384)   // 45056 -> 176 KB

// ---------------- kernel 2: fused interaction per (b,a) ----------------
__global__ void __launch_bounds__(256, 1) k_main(
    const float* __restrict__ r_ij, const float* __restrict__ cos_ij,
    const float* __restrict__ f_ij, const float* __restrict__ nmask,
    const float* __restrict__ fW1, const float* __restrict__ fb1,
    const float* __restrict__ fW2, const float* __restrict__ fb2,
    const float* __restrict__ f2oW, const float* __restrict__ f2ob,
    const float* __restrict__ aW1, const float* __restrict__ ab1,
    const float* __restrict__ aW2, const float* __restrict__ ab2,
    const float* __restrict__ pW1, const float* __restrict__ pb1,
    const float* __restrict__ pW2, const float* __restrict__ pb2,
    const float* __restrict__ eW1, const float* __restrict__ eb1,
    const float* __restrict__ eW2, const float* __restrict__ eb2,
    const int* __restrict__ neighbors, float* __restrict__ out_vi)
{
    extern __shared__ float smem[];
    float* sFT = smem + OFF_FT;   // [50][66] transposed filter features
    float* sA  = smem + OFF_A;    // [128][66]
    float* sB  = smem + OFF_B;    // [128][66]
    float* sV  = smem + OFF_V;    // [128][66]
    float* sW  = smem + OFF_W;    // [128][128]
    __shared__ float sMask[NN], sCut[NN], sCos[NN*3], vsum[NF], hid[NF];
    __shared__ int   sNbr[NN];

    int ba  = blockIdx.x;
    int b   = ba >> 8;
    int tid = threadIdx.x;

    // prefetch first weight matrix immediately
    for (int i = tid*4; i < NSB*NF; i += 1024)
        cp_async16(sW + i, fW1 + i);
    asm volatile("cp.async.commit_group;" ::: "memory");

    // load features transposed: sFT[s*66 + n] = f_ij[ba, n, s]
    const float* fg = f_ij + (size_t)ba * NN * NSB;
    for (int i = tid; i < NN*NSB; i += 256) {
        int n = i / NSB, s = i - n*NSB;
        sFT[s*66 + n] = fg[i];
    }
    if (tid < NN) {
        float r = r_ij[ba*NN + tid];
        sCut[tid]  = (r < 5.f) ? 0.5f * (cosf(r * 0.62831853071795864f) + 1.f) : 0.f;
        sMask[tid] = nmask[ba*NN + tid];
        sNbr[tid]  = neighbors[ba*NN + tid];
    }
    if (tid < NN*3) sCos[tid] = cos_ij[(size_t)ba*NN*3 + tid];
    asm volatile("cp.async.wait_group 0;" ::: "memory");
    __syncthreads();

    // --- filter net ---
    gemm_t<NSB, 0>(sFT, sW, fb1, sA, nullptr, fW2, NF*NF, sW);
    gemm_t<NF,  1>(sA,  sW, fb2, sB, sCut,    f2oW, NF*NF, sW);   // sB = Wf (transposed)

    // --- gather yj and multiply elementwise (transposed layout) ---
    for (int i = tid; i < NN*NF; i += 256) {
        int n = i >> 7, c = i & 127;
        sA[c*66 + n] = d_y[(size_t)((b << 8) + sNbr[n]) * NF + c] * sB[c*66 + n];
    }
    __syncthreads();

    // --- v = ssp((yj*Wf) @ f2out + b) ---
    gemm_t<NF, 0>(sA, sW, f2ob, sV, nullptr, pW1, NF*NF, sW);

    // --- pair MLP -> vij ---
    gemm_t<NF, 0>(sV, sW, pb1, sA, nullptr, pW2, NF*NF, sW);
    gemm_t<NF, 2>(sA, sW, pb2, sB, nullptr, eW1, NF*NF, sW);
    {
        float* vg = d_vij + (size_t)ba * NN * NCB;
        for (int i = tid; i < NN*NCB; i += 256) {
            int n = i >> 7, c = i & 127;
            vg[i] = sB[c*66 + n];
        }
    }

    // --- env MLP -> vik ---
    gemm_t<NF, 0>(sV, sW, eb1, sA, nullptr, eW2, NF*NF, sW);
    gemm_t<NF, 2>(sA, sW, eb2, sB, nullptr, nullptr, 0, sW);   // sB = vik (transposed)

    // --- Vik[c,d] = sum_n vik[n,c]*cos[n,d]*mask[n] ---
    for (int e = tid; e < NCB*3; e += 256) {
        int c = e / 3, d = e - c*3;
        float s = 0.f;
        #pragma unroll 4
        for (int n = 0; n < NN; n++)
            s = fmaf(sB[c*66 + n], sCos[n*3 + d] * sMask[n], s);
        d_Vik[(size_t)ba * (NCB*3) + e] = s;
    }
    // --- vsum[c] = sum_n v[n,c]*mask[n] ---
    if (tid < NF) {
        float s = 0.f;
        #pragma unroll 4
        for (int n = 0; n < NN; n++)
            s = fmaf(sV[tid*66 + n], sMask[n], s);
        vsum[tid] = s;
    }
    __syncthreads();
    // --- vi = mlp2(vsum, atom) ---
    if (tid < NF) {
        float h = ab1[tid];
        #pragma unroll 4
        for (int k = 0; k < NF; k++) h = fmaf(vsum[k], aW1[k*NF + tid], h);
        hid[tid] = sspf(h);
    }
    __syncthreads();
    if (tid < NF) {
        float o = ab2[tid];
        #pragma unroll 4
        for (int k = 0; k < NF; k++) o = fmaf(hid[k], aW2[k*NF + tid], o);
        out_vi[(size_t)ba * NF + tid] = o;
    }
}

// ---------------- kernel 3: assemble V ----------------
__global__ void k_assemble(const float* __restrict__ cos_ij,
                           const int* __restrict__ neighbors,
                           float* __restrict__ outV) {
    int idx = blockIdx.x;            // (b,a,n) flat, 65536
    int tid = threadIdx.x;           // channel c, 0..127
    int ba  = idx >> 6;
    int b   = idx >> 14;
    int nb  = neighbors[idx];
    float c0 = cos_ij[(size_t)idx*3 + 0];
    float c1 = cos_ij[(size_t)idx*3 + 1];
    float c2 = cos_ij[(size_t)idx*3 + 2];
    float vij = d_vij[(size_t)idx * NCB + tid];
    const float* vl = d_Vik + (size_t)ba * (NCB*3) + tid*3;
    const float* vn = d_Vik + ((size_t)(b*AA + nb)) * (NCB*3) + tid*3;
    float* o = outV + (size_t)idx * (NCB*3) + tid*3;
    o[0] = fmaf(vij, c0, vl[0] + vn[0]);
    o[1] = fmaf(vij, c1, vl[1] + vn[1]);
    o[2] = fmaf(vij, c2, vl[2] + vn[2]);
}

// ---------------- launch ----------------
extern "C" void kernel_launch(void* const* d_in, const int* in_sizes, int n_in,
                              void* d_out, int out_size) {
    const float* xi       = (const float*)d_in[0];
    const float* r_ij     = (const float*)d_in[1];
    const float* cos_ij   = (const float*)d_in[2];
    const float* f_ij     = (const float*)d_in[3];
    const float* nmask    = (const float*)d_in[4];
    const float* fW1      = (const float*)d_in[5];
    const float* fb1      = (const float*)d_in[6];
    const float* fW2      = (const float*)d_in[7];
    const float* fb2      = (const float*)d_in[8];
    const float* in2f_W   = (const float*)d_in[9];
    const float* f2oW     = (const float*)d_in[10];
    const float* f2ob     = (const float*)d_in[11];
    const float* aW1      = (const float*)d_in[12];
    const float* ab1      = (const float*)d_in[13];
    const float* aW2      = (const float*)d_in[14];
    const float* ab2      = (const float*)d_in[15];
    const float* pW1      = (const float*)d_in[16];
    const float* pb1      = (const float*)d_in[17];
    const float* pW2      = (const float*)d_in[18];
    const float* pb2      = (const float*)d_in[19];
    const float* eW1      = (const float*)d_in[20];
    const float* eb1      = (const float*)d_in[21];
    const float* eW2      = (const float*)d_in[22];
    const float* eb2      = (const float*)d_in[23];
    const int*   neighbors= (const int*)d_in[24];

    float* out = (float*)d_out;
    float* out_vi = out;                         // [B,A,NCB]
    float* out_V  = out + (size_t)BB*AA*NCB;     // [B,A,N,NCB,3]

    static const size_t SMEM_BYTES = SMEM_FLOATS * sizeof(float);  // 176 KB
    cudaFuncSetAttribute(k_main, cudaFuncAttributeMaxDynamicSharedMemorySize,
                         (int)SMEM_BYTES);

    k_embed<<<BB*AA, NF>>>(xi, in2f_W);
    k_main<<<BB*AA, 256, SMEM_BYTES>>>(
        r_ij, cos_ij, f_ij, nmask,
        fW1, fb1, fW2, fb2, f2oW, f2ob,
        aW1, ab1, aW2, ab2, pW1, pb1, pW2, pb2,
        eW1, eb1, eW2, eb2, neighbors, out_vi);
    k_assemble<<<BB*AA*NN, NF>>>(cos_ij, neighbors, out_V);
}

// round 4
// speedup vs baseline: 1.9228x; 1.7056x over previous
#include <cuda_runtime.h>
#include <cuda_bf16.h>
#include <math.h>
#include <stdint.h>

#define BB  4
#define AA  256
#define NN  64
#define NCB 128
#define NF  128
#define NSB 50

#define PITCH 136                    // bf16 elems per row (conflict-free frags)
#define IMG   (128 * PITCH * 2)      // bytes per bf16 image (34816)

// ---------------- global scratch (no allocs allowed) ----------------
__device__ float d_y[BB*AA*NF];                         // xi @ in2f_W
__device__ float d_vij[(size_t)BB*AA*NN*NCB];           // pair output (32 MB)
__device__ float d_Vik[BB*AA*NCB*3];                    // env reduction
__device__ __align__(16) __nv_bfloat16 d_wsplit[7 * 2 * 128 * PITCH];

// ---------------- helpers ----------------
__device__ __forceinline__ void cp16(void* sdst, const void* gsrc) {
    unsigned s = (unsigned)__cvta_generic_to_shared(sdst);
    asm volatile("cp.async.cg.shared.global [%0], [%1], 16;" :: "r"(s), "l"(gsrc));
}
#define CP_COMMIT()  asm volatile("cp.async.commit_group;" ::: "memory")
#define CP_WAIT0()   asm volatile("cp.async.wait_group 0;" ::: "memory")

__device__ __forceinline__ uint32_t lds32(const char* p) {
    return *reinterpret_cast<const uint32_t*>(p);
}

__device__ __forceinline__ void mma16816(float* c, const uint32_t* a, const uint32_t* b) {
    asm volatile("mma.sync.aligned.m16n8k16.row.col.f32.bf16.bf16.f32 "
        "{%0,%1,%2,%3}, {%4,%5,%6,%7}, {%8,%9}, {%0,%1,%2,%3};"
        : "+f"(c[0]), "+f"(c[1]), "+f"(c[2]), "+f"(c[3])
        : "r"(a[0]), "r"(a[1]), "r"(a[2]), "r"(a[3]), "r"(b[0]), "r"(b[1]));
}

__device__ __forceinline__ float sspf(float x) {
    if (x > 15.f) return x - 0.69314718055994531f;
    return __logf(1.f + __expf(x)) - 0.69314718055994531f;
}
__device__ __forceinline__ void split2(float v0, float v1, uint32_t& hi, uint32_t& lo) {
    __nv_bfloat16 h0 = __float2bfloat16(v0);
    __nv_bfloat16 h1 = __float2bfloat16(v1);
    float l0 = v0 - __bfloat162float(h0);
    float l1 = v1 - __bfloat162float(h1);
    __nv_bfloat162 hp; hp.x = h0; hp.y = h1;
    __nv_bfloat162 lp = __floats2bfloat162_rn(l0, l1);
    hi = *reinterpret_cast<uint32_t*>(&hp);
    lo = *reinterpret_cast<uint32_t*>(&lp);
}

// ---------------- kernel: weight prep (transpose + split, [n][k] pitch 136) ----
__global__ void k_prep(const float* fW1, const float* fW2, const float* f2oW,
                       const float* pW1, const float* pW2,
                       const float* eW1, const float* eW2) {
    int s = blockIdx.x;
    const float* W; int K, realK;
    switch (s) {
        case 0: W = fW1;  K = 64;  realK = NSB; break;
        case 1: W = fW2;  K = 128; realK = 128; break;
        case 2: W = f2oW; K = 128; realK = 128; break;
        case 3: W = pW1;  K = 128; realK = 128; break;
        case 4: W = pW2;  K = 128; realK = 128; break;
        case 5: W = eW1;  K = 128; realK = 128; break;
        default: W = eW2; K = 128; realK = 128; break;
    }
    __nv_bfloat16* hi = d_wsplit + (size_t)s * 2 * 128 * PITCH;
    __nv_bfloat16* lo = hi + 128 * PITCH;
    for (int i = threadIdx.x; i < 128 * K; i += blockDim.x) {
        int n = i / K, k = i - (i / K) * K;
        float v = (k < realK) ? W[k * 128 + n] : 0.f;    // B^T: [n][k]
        __nv_bfloat16 h = __float2bfloat16(v);
        float l = v - __bfloat162float(h);
        hi[n * PITCH + k] = h;
        lo[n * PITCH + k] = __float2bfloat16(l);
    }
}

// ---------------- kernel: per-atom embedding ----------------
__global__ void k_embed(const float* __restrict__ xi, const float* __restrict__ W) {
    int row = blockIdx.x;
    int c   = threadIdx.x;
    __shared__ float sx[NF];
    sx[c] = xi[(size_t)row*NF + c];
    __syncthreads();
    float acc = 0.f;
    #pragma unroll 8
    for (int k = 0; k < NF; k++)
        acc = fmaf(sx[k], W[k*NF + c], acc);
    d_y[(size_t)row*NF + c] = acc;
}

// ---------------- SMEM byte layout ----------------
#define AH_OFF 0u
#define AL_OFF ((uint32_t)IMG)
#define VH_OFF ((uint32_t)(2*IMG))
#define VL_OFF ((uint32_t)(3*IMG))
#define WH_OFF ((uint32_t)(4*IMG))
#define SMEM_BYTES ((uint32_t)(6*IMG))   // 208896

// split-bf16 GEMM compute: acc += A[128xK] @ W^T, warp tile m64 n32
template<int KSTEPS>
__device__ __forceinline__ void mm_compute(const char* __restrict__ aH,
                                           const char* __restrict__ wH,
                                           float acc[4][4][4],
                                           int warp_m, int warp_n, int lane) {
    const int er  = lane >> 2;
    const int ec2 = (lane & 3) * 2;
    const char* aBase = aH + ((warp_m*64 + er) * PITCH + ec2) * 2;
    const char* wBase = wH + ((warp_n*32 + er) * PITCH + ec2) * 2;
    #pragma unroll 1
    for (int kk = 0; kk < KSTEPS; kk++) {
        uint32_t Ah[4][4], Al[4][4], Wh[4][2], Wl[4][2];
        const char* ak = aBase + kk * 32;
        const char* wk = wBase + kk * 32;
        #pragma unroll
        for (int mt = 0; mt < 4; mt++) {
            const char* p = ak + mt * (16 * PITCH * 2);
            Ah[mt][0] = lds32(p);
            Ah[mt][1] = lds32(p + 8*PITCH*2);
            Ah[mt][2] = lds32(p + 16);
            Ah[mt][3] = lds32(p + 8*PITCH*2 + 16);
            const char* q = p + IMG;
            Al[mt][0] = lds32(q);
            Al[mt][1] = lds32(q + 8*PITCH*2);
            Al[mt][2] = lds32(q + 16);
            Al[mt][3] = lds32(q + 8*PITCH*2 + 16);
        }
        #pragma unroll
        for (int nt = 0; nt < 4; nt++) {
            const char* p = wk + nt * (8 * PITCH * 2);
            Wh[nt][0] = lds32(p);
            Wh[nt][1] = lds32(p + 16);
            const char* q = p + IMG;
            Wl[nt][0] = lds32(q);
            Wl[nt][1] = lds32(q + 16);
        }
        #pragma unroll
        for (int mt = 0; mt < 4; mt++)
            #pragma unroll
            for (int nt = 0; nt < 4; nt++) {
                mma16816(acc[mt][nt], Ah[mt], Wh[nt]);
                mma16816(acc[mt][nt], Ah[mt], Wl[nt]);
                mma16816(acc[mt][nt], Al[mt], Wh[nt]);
            }
    }
}

// ---------------- kernel: fused interaction, 2 atoms per CTA ----------------
__global__ void __launch_bounds__(256, 1) k_main(
    const float* __restrict__ r_ij, const float* __restrict__ cos_ij,
    const float* __restrict__ f_ij, const float* __restrict__ nmask,
    const float* __restrict__ fb1, const float* __restrict__ fb2,
    const float* __restrict__ f2ob,
    const float* __restrict__ aW1, const float* __restrict__ ab1,
    const float* __restrict__ aW2, const float* __restrict__ ab2,
    const float* __restrict__ pb1, const float* __restrict__ pb2,
    const float* __restrict__ eb1, const float* __restrict__ eb2,
    const int* __restrict__ neighbors, float* __restrict__ out_vi)
{
    extern __shared__ char smem[];
    const int tid = threadIdx.x, wid = tid >> 5, lane = tid & 31;
    const int warp_m = wid & 1, warp_n = wid >> 1;
    const int ba0 = blockIdx.x * 2;
    const int b   = ba0 >> 8;

    __shared__ float sCut[128], sMask[128], cmS[128*3], vsumS[256], hidS[256];
    __shared__ int   sNbr[128];

    // prefetch stage-0 weights
    {
        const char* src = reinterpret_cast<const char*>(d_wsplit);
        for (int i = tid * 16; i < 2*IMG; i += 4096)
            cp16(smem + WH_OFF + i, src + i);
        CP_COMMIT();
    }

    // per-row scalars (rows 0..127 = 2 atoms x 64 neighbors)
    if (tid < 128) {
        int g = ba0 * NN + tid;
        float r = r_ij[g];
        sCut[tid]  = (r < 5.f) ? 0.5f * (__cosf(r * 0.62831853071795864f) + 1.f) : 0.f;
        float m = nmask[g];
        sMask[tid] = m;
        sNbr[tid]  = neighbors[g];
        cmS[tid*3+0] = cos_ij[(size_t)g*3+0] * m;
        cmS[tid*3+1] = cos_ij[(size_t)g*3+1] * m;
        cmS[tid*3+2] = cos_ij[(size_t)g*3+2] * m;
    }

    // zero A images, then scatter split features
    {
        uint64_t* z = reinterpret_cast<uint64_t*>(smem + AH_OFF);
        for (int i = tid; i < (2*IMG)/8; i += 256) z[i] = 0ull;
    }
    __syncthreads();
    {
        const float* fg = f_ij + (size_t)ba0 * NN * NSB;
        __nv_bfloat16* ah = reinterpret_cast<__nv_bfloat16*>(smem + AH_OFF);
        __nv_bfloat16* al = reinterpret_cast<__nv_bfloat16*>(smem + AL_OFF);
        for (int i = tid; i < 128 * NSB; i += 256) {
            int r = i / NSB, c = i - (i / NSB) * NSB;
            float v = fg[i];
            __nv_bfloat16 h = __float2bfloat16(v);
            ah[r * PITCH + c] = h;
            al[r * PITCH + c] = __float2bfloat16(v - __bfloat162float(h));
        }
    }
    CP_WAIT0();
    __syncthreads();

    const float* biases[7] = {fb1, fb2, f2ob, pb1, pb2, eb1, eb2};
    const int er  = lane >> 2;
    const int ec2 = (lane & 3) * 2;
    float* vikT = reinterpret_cast<float*>(smem + WH_OFF);   // reused at s==6

    for (int s = 0; s < 7; s++) {
        const char* aBase = smem + ((s == 3 || s == 5) ? VH_OFF : AH_OFF);
        float acc[4][4][4];
        #pragma unroll
        for (int mt = 0; mt < 4; mt++)
            #pragma unroll
            for (int nt = 0; nt < 4; nt++)
                #pragma unroll
                for (int j = 0; j < 4; j++) acc[mt][nt][j] = 0.f;

        if (s == 0) mm_compute<4>(aBase, smem + WH_OFF, acc, warp_m, warp_n, lane);
        else        mm_compute<8>(aBase, smem + WH_OFF, acc, warp_m, warp_n, lane);

        __syncthreads();   // all warps done reading A and W

        if (s < 6) {       // prefetch next-stage weights (overlaps epilogue)
            const char* src = reinterpret_cast<const char*>(
                d_wsplit + (size_t)(s + 1) * 2 * 128 * PITCH);
            for (int i = tid * 16; i < 2*IMG; i += 4096)
                cp16(smem + WH_OFF + i, src + i);
            CP_COMMIT();
        }

        // ---- epilogue ----
        const float* bias = biases[s];
        char* dstH = smem + ((s == 2) ? VH_OFF : AH_OFF);
        #pragma unroll
        for (int mt = 0; mt < 4; mt++) {
            int row0 = warp_m*64 + mt*16 + er;
            #pragma unroll
            for (int nt = 0; nt < 4; nt++) {
                int col = warp_n*32 + nt*8 + ec2;
                float b0 = __ldg(bias + col), b1 = __ldg(bias + col + 1);
                #pragma unroll
                for (int h = 0; h < 2; h++) {
                    int row = row0 + h*8;
                    float x0 = acc[mt][nt][h*2+0] + b0;
                    float x1 = acc[mt][nt][h*2+1] + b1;
                    if (s == 1) {
                        float cu = sCut[row];
                        const float2 y = *reinterpret_cast<const float2*>(
                            d_y + ((size_t)((b << 8) + sNbr[row]) << 7) + col);
                        x0 = x0 * cu * y.x;
                        x1 = x1 * cu * y.y;
                    } else if (s == 4) {
                        *reinterpret_cast<float2*>(
                            d_vij + ((size_t)ba0 * 64 + row) * 128 + col) =
                            make_float2(x0, x1);
                        continue;
                    } else if (s == 6) {
                        vikT[col * PITCH + row]       = x0;
                        vikT[(col + 1) * PITCH + row] = x1;
                        continue;
                    } else {
                        x0 = sspf(x0); x1 = sspf(x1);
                    }
                    uint32_t hp, lp;
                    split2(x0, x1, hp, lp);
                    uint32_t off = (uint32_t)(row * PITCH + col) * 2;
                    *reinterpret_cast<uint32_t*>(dstH + off)       = hp;
                    *reinterpret_cast<uint32_t*>(dstH + IMG + off) = lp;
                }
            }
        }

        if (s < 6) CP_WAIT0();
        __syncthreads();
    }

    // ---- Vik reduction (vikT lives in W buffer) ----
    for (int e = tid; e < 768; e += 256) {
        int atom = e / 384, rem = e - atom * 384;
        int c = rem / 3, d = rem - c * 3;
        float s = 0.f;
        #pragma unroll 4
        for (int n = 0; n < 64; n++) {
            int r = atom * 64 + n;
            s = fmaf(vikT[c * PITCH + r], cmS[r * 3 + d], s);
        }
        d_Vik[(size_t)(ba0 + atom) * (NCB*3) + c * 3 + d] = s;
    }

    // ---- vsum from V, atom MLP -> out_vi ----
    {
        int atom = tid >> 7, c = tid & 127;
        const __nv_bfloat16* vh = reinterpret_cast<const __nv_bfloat16*>(smem + VH_OFF);
        const __nv_bfloat16* vl = reinterpret_cast<const __nv_bfloat16*>(smem + VL_OFF);
        float s = 0.f;
        #pragma unroll 4
        for (int n = 0; n < 64; n++) {
            int r = atom * 64 + n;
            float v = __bfloat162float(vh[r * PITCH + c])
                    + __bfloat162float(vl[r * PITCH + c]);
            s = fmaf(v, sMask[r], s);
        }
        vsumS[tid] = s;
    }
    __syncthreads();
    {
        int atom = tid >> 7, c = tid & 127;
        float h = __ldg(ab1 + c);
        #pragma unroll 4
        for (int k = 0; k < 128; k++)
            h = fmaf(vsumS[atom * 128 + k], __ldg(aW1 + k * 128 + c), h);
        hidS[tid] = sspf(h);
    }
    __syncthreads();
    {
        int atom = tid >> 7, c = tid & 127;
        float o = __ldg(ab2 + c);
        #pragma unroll 4
        for (int k = 0; k < 128; k++)
            o = fmaf(hidS[atom * 128 + k], __ldg(aW2 + k * 128 + c), o);
        out_vi[(size_t)(ba0 + atom) * NF + c] = o;
    }
}

// ---------------- kernel: assemble V ----------------
__global__ void k_assemble(const float* __restrict__ cos_ij,
                           const int* __restrict__ neighbors,
                           float* __restrict__ outV) {
    int idx = blockIdx.x;            // (b,a,n) flat
    int tid = threadIdx.x;           // channel c
    int ba  = idx >> 6;
    int b   = idx >> 14;
    int nb  = neighbors[idx];
    float c0 = cos_ij[(size_t)idx*3 + 0];
    float c1 = cos_ij[(size_t)idx*3 + 1];
    float c2 = cos_ij[(size_t)idx*3 + 2];
    float vij = d_vij[(size_t)idx * NCB + tid];
    const float* vl = d_Vik + (size_t)ba * (NCB*3) + tid*3;
    const float* vn = d_Vik + ((size_t)(b*AA + nb)) * (NCB*3) + tid*3;
    float* o = outV + (size_t)idx * (NCB*3) + tid*3;
    o[0] = fmaf(vij, c0, vl[0] + vn[0]);
    o[1] = fmaf(vij, c1, vl[1] + vn[1]);
    o[2] = fmaf(vij, c2, vl[2] + vn[2]);
}

// ---------------- launch ----------------
extern "C" void kernel_launch(void* const* d_in, const int* in_sizes, int n_in,
                              void* d_out, int out_size) {
    const float* xi       = (const float*)d_in[0];
    const float* r_ij     = (const float*)d_in[1];
    const float* cos_ij   = (const float*)d_in[2];
    const float* f_ij     = (const float*)d_in[3];
    const float* nmask    = (const float*)d_in[4];
    const float* fW1      = (const float*)d_in[5];
    const float* fb1      = (const float*)d_in[6];
    const float* fW2      = (const float*)d_in[7];
    const float* fb2      = (const float*)d_in[8];
    const float* in2f_W   = (const float*)d_in[9];
    const float* f2oW     = (const float*)d_in[10];
    const float* f2ob     = (const float*)d_in[11];
    const float* aW1      = (const float*)d_in[12];
    const float* ab1      = (const float*)d_in[13];
    const float* aW2      = (const float*)d_in[14];
    const float* ab2      = (const float*)d_in[15];
    const float* pW1      = (const float*)d_in[16];
    const float* pb1      = (const float*)d_in[17];
    const float* pW2      = (const float*)d_in[18];
    const float* pb2      = (const float*)d_in[19];
    const float* eW1      = (const float*)d_in[20];
    const float* eb1      = (const float*)d_in[21];
    const float* eW2      = (const float*)d_in[22];
    const float* eb2      = (const float*)d_in[23];
    const int*   neighbors= (const int*)d_in[24];

    float* out = (float*)d_out;
    float* out_vi = out;                          // [B,A,NCB]
    float* out_V  = out + (size_t)BB*AA*NCB;      // [B,A,N,NCB,3]

    cudaFuncSetAttribute(k_main, cudaFuncAttributeMaxDynamicSharedMemorySize,
                         (int)SMEM_BYTES);

    k_prep<<<7, 256>>>(fW1, fW2, f2oW, pW1, pW2, eW1, eW2);
    k_embed<<<BB*AA, NF>>>(xi, in2f_W);
    k_main<<<BB*AA/2, 256, SMEM_BYTES>>>(
        r_ij, cos_ij, f_ij, nmask,
        fb1, fb2, f2ob, aW1, ab1, aW2, ab2,
        pb1, pb2, eb1, eb2, neighbors, out_vi);
    k_assemble<<<BB*AA*NN, NF>>>(cos_ij, neighbors, out_V);
}

// round 5
// speedup vs baseline: 1.9664x; 1.0227x over previous
#include <cuda_runtime.h>
#include <cuda_fp16.h>
#include <math.h>
#include <stdint.h>

#define BB  4
#define AA  256
#define NN  64
#define NCB 128
#define NF  128
#define NSB 50

#define PITCH 136                    // fp16 elems per row
#define IMG   (128 * PITCH * 2)      // bytes per fp16 image (34816)

// ---------------- global scratch (no allocs allowed) ----------------
__device__ float d_y[BB*AA*NF];                         // xi @ in2f_W
__device__ float d_vij[(size_t)BB*AA*NN*NCB];           // pair output (32 MB)
__device__ float d_Vik[BB*AA*NCB*3];                    // env reduction
__device__ __align__(16) __half d_wsplit[7 * 2 * 128 * PITCH];

// ---------------- helpers ----------------
__device__ __forceinline__ void cp16(void* sdst, const void* gsrc) {
    unsigned s = (unsigned)__cvta_generic_to_shared(sdst);
    asm volatile("cp.async.cg.shared.global [%0], [%1], 16;" :: "r"(s), "l"(gsrc));
}
#define CP_COMMIT()  asm volatile("cp.async.commit_group;" ::: "memory")
#define CP_WAIT0()   asm volatile("cp.async.wait_group 0;" ::: "memory")

__device__ __forceinline__ void ldsm4(uint32_t* r, uint32_t saddr) {
    asm volatile("ldmatrix.sync.aligned.m8n8.x4.shared.b16 {%0,%1,%2,%3}, [%4];"
        : "=r"(r[0]), "=r"(r[1]), "=r"(r[2]), "=r"(r[3]) : "r"(saddr));
}

__device__ __forceinline__ void mma16816(float* c, const uint32_t* a,
                                         uint32_t b0, uint32_t b1) {
    asm volatile("mma.sync.aligned.m16n8k16.row.col.f32.f16.f16.f32 "
        "{%0,%1,%2,%3}, {%4,%5,%6,%7}, {%8,%9}, {%0,%1,%2,%3};"
        : "+f"(c[0]), "+f"(c[1]), "+f"(c[2]), "+f"(c[3])
        : "r"(a[0]), "r"(a[1]), "r"(a[2]), "r"(a[3]), "r"(b0), "r"(b1));
}

__device__ __forceinline__ float sspf(float x) {
    if (x > 15.f) return x - 0.69314718055994531f;
    return __logf(1.f + __expf(x)) - 0.69314718055994531f;
}
__device__ __forceinline__ void split2h(float v0, float v1, uint32_t& hi, uint32_t& lo) {
    __half h0 = __float2half_rn(v0);
    __half h1 = __float2half_rn(v1);
    float l0 = v0 - __half2float(h0);
    float l1 = v1 - __half2float(h1);
    __half2 hp; hp.x = h0; hp.y = h1;
    __half2 lp = __floats2half2_rn(l0, l1);
    hi = *reinterpret_cast<uint32_t*>(&hp);
    lo = *reinterpret_cast<uint32_t*>(&lp);
}

// ---------------- kernel: weight prep (transpose + fp16 split, [n][k]) ------
__global__ void k_prep(const float* fW1, const float* fW2, const float* f2oW,
                       const float* pW1, const float* pW2,
                       const float* eW1, const float* eW2) {
    int s = blockIdx.x;
    const float* W; int K, realK;
    switch (s) {
        case 0: W = fW1;  K = 64;  realK = NSB; break;
        case 1: W = fW2;  K = 128; realK = 128; break;
        case 2: W = f2oW; K = 128; realK = 128; break;
        case 3: W = pW1;  K = 128; realK = 128; break;
        case 4: W = pW2;  K = 128; realK = 128; break;
        case 5: W = eW1;  K = 128; realK = 128; break;
        default: W = eW2; K = 128; realK = 128; break;
    }
    __half* hi = d_wsplit + (size_t)s * 2 * 128 * PITCH;
    __half* lo = hi + 128 * PITCH;
    for (int i = threadIdx.x; i < 128 * K; i += blockDim.x) {
        int n = i / K, k = i - (i / K) * K;
        float v = (k < realK) ? W[k * 128 + n] : 0.f;    // B^T: [n][k]
        __half h = __float2half_rn(v);
        hi[n * PITCH + k] = h;
        lo[n * PITCH + k] = __float2half_rn(v - __half2float(h));
    }
}

// ---------------- kernel: per-atom embedding (4 rows / block) --------------
__global__ void k_embed(const float* __restrict__ xi, const float* __restrict__ W) {
    int row0 = blockIdx.x * 4;
    int c = threadIdx.x;          // 0..127
    __shared__ float sx[4][128];
    #pragma unroll
    for (int r = 0; r < 4; r++) sx[r][c] = xi[(size_t)(row0 + r) * 128 + c];
    __syncthreads();
    float a0 = 0.f, a1 = 0.f, a2 = 0.f, a3 = 0.f;
    #pragma unroll 4
    for (int k = 0; k < 128; k++) {
        float w = __ldg(W + k * 128 + c);
        a0 = fmaf(sx[0][k], w, a0);
        a1 = fmaf(sx[1][k], w, a1);
        a2 = fmaf(sx[2][k], w, a2);
        a3 = fmaf(sx[3][k], w, a3);
    }
    d_y[(size_t)(row0 + 0) * 128 + c] = a0;
    d_y[(size_t)(row0 + 1) * 128 + c] = a1;
    d_y[(size_t)(row0 + 2) * 128 + c] = a2;
    d_y[(size_t)(row0 + 3) * 128 + c] = a3;
}

// ---------------- SMEM byte layout ----------------
#define AH_OFF 0u
#define AL_OFF ((uint32_t)IMG)
#define VH_OFF ((uint32_t)(2*IMG))
#define VL_OFF ((uint32_t)(3*IMG))
#define WH_OFF ((uint32_t)(4*IMG))
#define SMEM_BYTES ((uint32_t)(6*IMG))   // 208896

// split-fp16 GEMM: acc += A[128xK] @ W^T, 16 warps, warp tile m32 n32, ldmatrix
template<int KSTEPS>
__device__ __forceinline__ void mm_compute(uint32_t aH, uint32_t wH,
                                           float acc[2][4][4],
                                           int warp_m, int warp_n, int lane) {
    const int rsel = lane & 15, hsel = lane >> 4;
    uint32_t aAddr = aH + (uint32_t)(((warp_m*32 + rsel) * PITCH + hsel*8) * 2);
    uint32_t wAddr = wH + (uint32_t)(((warp_n*32 + rsel) * PITCH + hsel*8) * 2);
    const uint32_t STEP16 = 16 * PITCH * 2;
    #pragma unroll 1
    for (int kk = 0; kk < KSTEPS; kk++) {
        uint32_t Ah[2][4], Al[2][4], Wh[2][4], Wl[2][4];
        uint32_t ak = aAddr + kk * 32;
        uint32_t wk = wAddr + kk * 32;
        ldsm4(Ah[0], ak);
        ldsm4(Ah[1], ak + STEP16);
        ldsm4(Al[0], ak + IMG);
        ldsm4(Al[1], ak + IMG + STEP16);
        ldsm4(Wh[0], wk);
        ldsm4(Wh[1], wk + STEP16);
        ldsm4(Wl[0], wk + IMG);
        ldsm4(Wl[1], wk + IMG + STEP16);
        #pragma unroll
        for (int mt = 0; mt < 2; mt++)
            #pragma unroll
            for (int ng = 0; ng < 2; ng++)
                #pragma unroll
                for (int j = 0; j < 2; j++) {
                    int nt = ng * 2 + j;
                    mma16816(acc[mt][nt], Ah[mt], Wh[ng][j], Wh[ng][j+2]);
                    mma16816(acc[mt][nt], Ah[mt], Wl[ng][j], Wl[ng][j+2]);
                    mma16816(acc[mt][nt], Al[mt], Wh[ng][j], Wh[ng][j+2]);
                }
    }
}

// ---------------- kernel: fused interaction, 2 atoms per CTA ----------------
__global__ void __launch_bounds__(512, 1) k_main(
    const float* __restrict__ r_ij, const float* __restrict__ cos_ij,
    const float* __restrict__ f_ij, const float* __restrict__ nmask,
    const float* __restrict__ fb1, const float* __restrict__ fb2,
    const float* __restrict__ f2ob,
    const float* __restrict__ aW1, const float* __restrict__ ab1,
    const float* __restrict__ aW2, const float* __restrict__ ab2,
    const float* __restrict__ pb1, const float* __restrict__ pb2,
    const float* __restrict__ eb1, const float* __restrict__ eb2,
    const int* __restrict__ neighbors, float* __restrict__ out_vi)
{
    extern __shared__ char smem[];
    const uint32_t sb = (uint32_t)__cvta_generic_to_shared(smem);
    const int tid = threadIdx.x, wid = tid >> 5, lane = tid & 31;
    const int warp_m = wid & 3, warp_n = wid >> 2;
    const int ba0 = blockIdx.x * 2;
    const int b   = ba0 >> 8;

    __shared__ float sCut[128], sMask[128], cmS[128*3], vsumS[256], hidS[256];
    __shared__ int   sNbr[128];

    // prefetch stage-0 weights
    {
        const char* src = reinterpret_cast<const char*>(d_wsplit);
        for (int i = tid * 16; i < 2*IMG; i += 512*16)
            cp16(smem + WH_OFF + i, src + i);
        CP_COMMIT();
    }

    if (tid < 128) {
        int g = ba0 * NN + tid;
        float r = r_ij[g];
        sCut[tid]  = (r < 5.f) ? 0.5f * (__cosf(r * 0.62831853071795864f) + 1.f) : 0.f;
        float m = nmask[g];
        sMask[tid] = m;
        sNbr[tid]  = neighbors[g];
        cmS[tid*3+0] = cos_ij[(size_t)g*3+0] * m;
        cmS[tid*3+1] = cos_ij[(size_t)g*3+1] * m;
        cmS[tid*3+2] = cos_ij[(size_t)g*3+2] * m;
    }

    {   // zero A images
        uint64_t* z = reinterpret_cast<uint64_t*>(smem + AH_OFF);
        for (int i = tid; i < (2*IMG)/8; i += 512) z[i] = 0ull;
    }
    __syncthreads();
    {   // scatter split features
        const float* fg = f_ij + (size_t)ba0 * NN * NSB;
        __half* ah = reinterpret_cast<__half*>(smem + AH_OFF);
        __half* al = reinterpret_cast<__half*>(smem + AL_OFF);
        for (int i = tid; i < 128 * NSB; i += 512) {
            int r = i / NSB, c = i - (i / NSB) * NSB;
            float v = fg[i];
            __half h = __float2half_rn(v);
            ah[r * PITCH + c] = h;
            al[r * PITCH + c] = __float2half_rn(v - __half2float(h));
        }
    }
    CP_WAIT0();
    __syncthreads();

    const float* biases[7] = {fb1, fb2, f2ob, pb1, pb2, eb1, eb2};
    const int er  = lane >> 2;
    const int ec2 = (lane & 3) * 2;
    float* vikT = reinterpret_cast<float*>(smem + WH_OFF);   // reused at s==6

    for (int s = 0; s < 7; s++) {
        const uint32_t aBase = sb + ((s == 3 || s == 5) ? VH_OFF : AH_OFF);
        float acc[2][4][4];
        #pragma unroll
        for (int mt = 0; mt < 2; mt++)
            #pragma unroll
            for (int nt = 0; nt < 4; nt++)
                #pragma unroll
                for (int j = 0; j < 4; j++) acc[mt][nt][j] = 0.f;

        if (s == 0) mm_compute<4>(aBase, sb + WH_OFF, acc, warp_m, warp_n, lane);
        else        mm_compute<8>(aBase, sb + WH_OFF, acc, warp_m, warp_n, lane);

        __syncthreads();   // all warps done reading A and W

        if (s < 6) {       // prefetch next-stage weights (overlaps epilogue)
            const char* src = reinterpret_cast<const char*>(
                d_wsplit + (size_t)(s + 1) * 2 * 128 * PITCH);
            for (int i = tid * 16; i < 2*IMG; i += 512*16)
                cp16(smem + WH_OFF + i, src + i);
            CP_COMMIT();
        }

        // ---- epilogue ----
        const float* bias = biases[s];
        char* dstH = smem + ((s == 2) ? VH_OFF : AH_OFF);
        #pragma unroll
        for (int mt = 0; mt < 2; mt++) {
            int row0 = warp_m*32 + mt*16 + er;
            #pragma unroll
            for (int nt = 0; nt < 4; nt++) {
                int col = warp_n*32 + nt*8 + ec2;
                float b0 = __ldg(bias + col), b1 = __ldg(bias + col + 1);
                #pragma unroll
                for (int h = 0; h < 2; h++) {
                    int row = row0 + h*8;
                    float x0 = acc[mt][nt][h*2+0] + b0;
                    float x1 = acc[mt][nt][h*2+1] + b1;
                    if (s == 1) {
                        float cu = sCut[row];
                        const float2 y = *reinterpret_cast<const float2*>(
                            d_y + ((size_t)((b << 8) + sNbr[row]) << 7) + col);
                        x0 = x0 * cu * y.x;
                        x1 = x1 * cu * y.y;
                    } else if (s == 4) {
                        *reinterpret_cast<float2*>(
                            d_vij + ((size_t)ba0 * 64 + row) * 128 + col) =
                            make_float2(x0, x1);
                        continue;
                    } else if (s == 6) {
                        vikT[col * PITCH + row]       = x0;
                        vikT[(col + 1) * PITCH + row] = x1;
                        continue;
                    } else {
                        x0 = sspf(x0); x1 = sspf(x1);
                    }
                    uint32_t hp, lp;
                    split2h(x0, x1, hp, lp);
                    uint32_t off = (uint32_t)(row * PITCH + col) * 2;
                    *reinterpret_cast<uint32_t*>(dstH + off)       = hp;
                    *reinterpret_cast<uint32_t*>(dstH + IMG + off) = lp;
                }
            }
        }

        if (s < 6) CP_WAIT0();
        __syncthreads();
    }

    // ---- Vik reduction (vikT lives in W buffer) ----
    for (int e = tid; e < 768; e += 512) {
        int atom = e / 384, rem = e - atom * 384;
        int c = rem / 3, d = rem - c * 3;
        float s = 0.f;
        #pragma unroll 4
        for (int n = 0; n < 64; n++) {
            int r = atom * 64 + n;
            s = fmaf(vikT[c * PITCH + r], cmS[r * 3 + d], s);
        }
        d_Vik[(size_t)(ba0 + atom) * (NCB*3) + c * 3 + d] = s;
    }

    // ---- vsum from V, atom MLP -> out_vi (first 256 threads) ----
    if (tid < 256) {
        int atom = tid >> 7, c = tid & 127;
        const __half* vh = reinterpret_cast<const __half*>(smem + VH_OFF);
        const __half* vl = reinterpret_cast<const __half*>(smem + VL_OFF);
        float s = 0.f;
        #pragma unroll 4
        for (int n = 0; n < 64; n++) {
            int r = atom * 64 + n;
            float v = __half2float(vh[r * PITCH + c]) + __half2float(vl[r * PITCH + c]);
            s = fmaf(v, sMask[r], s);
        }
        vsumS[tid] = s;
    }
    __syncthreads();
    if (tid < 256) {
        int atom = tid >> 7, c = tid & 127;
        float h = __ldg(ab1 + c);
        #pragma unroll 4
        for (int k = 0; k < 128; k++)
            h = fmaf(vsumS[atom * 128 + k], __ldg(aW1 + k * 128 + c), h);
        hidS[tid] = sspf(h);
    }
    __syncthreads();
    if (tid < 256) {
        int atom = tid >> 7, c = tid & 127;
        float o = __ldg(ab2 + c);
        #pragma unroll 4
        for (int k = 0; k < 128; k++)
            o = fmaf(hidS[atom * 128 + k], __ldg(aW2 + k * 128 + c), o);
        out_vi[(size_t)(ba0 + atom) * NF + c] = o;
    }
}

// ---------------- kernel: assemble V (smem-staged, float4 stores) ----------
__global__ void __launch_bounds__(128) k_assemble(
    const float* __restrict__ cos_ij,
    const int* __restrict__ neighbors,
    float* __restrict__ outV) {
    __shared__ float svij[128];
    __shared__ float svs[384];
    __shared__ float sc[3];
    int idx = blockIdx.x;            // (b,a,n) flat
    int tid = threadIdx.x;
    int ba  = idx >> 6;
    int b   = idx >> 14;
    int nb  = __ldg(neighbors + idx);
    svij[tid] = d_vij[(size_t)idx * 128 + tid];
    const float* vl = d_Vik + (size_t)ba * 384;
    const float* vn = d_Vik + ((size_t)(b * AA + nb)) * 384;
    for (int i = tid; i < 384; i += 128) svs[i] = vl[i] + vn[i];
    if (tid < 3) sc[tid] = cos_ij[(size_t)idx * 3 + tid];
    __syncthreads();
    if (tid < 96) {
        int e0 = tid * 4;
        float4 o;
        float* op = reinterpret_cast<float*>(&o);
        #pragma unroll
        for (int j = 0; j < 4; j++) {
            int e = e0 + j;
            int c = e / 3, d = e - 3 * c;
            op[j] = fmaf(svij[c], sc[d], svs[e]);
        }
        *reinterpret_cast<float4*>(outV + (size_t)idx * 384 + e0) = o;
    }
}

// ---------------- launch ----------------
extern "C" void kernel_launch(void* const* d_in, const int* in_sizes, int n_in,
                              void* d_out, int out_size) {
    const float* xi       = (const float*)d_in[0];
    const float* r_ij     = (const float*)d_in[1];
    const float* cos_ij   = (const float*)d_in[2];
    const float* f_ij     = (const float*)d_in[3];
    const float* nmask    = (const float*)d_in[4];
    const float* fW1      = (const float*)d_in[5];
    const float* fb1      = (const float*)d_in[6];
    const float* fW2      = (const float*)d_in[7];
    const float* fb2      = (const float*)d_in[8];
    const float* in2f_W   = (const float*)d_in[9];
    const float* f2oW     = (const float*)d_in[10];
    const float* f2ob     = (const float*)d_in[11];
    const float* aW1      = (const float*)d_in[12];
    const float* ab1      = (const float*)d_in[13];
    const float* aW2      = (const float*)d_in[14];
    const float* ab2      = (const float*)d_in[15];
    const float* pW1      = (const float*)d_in[16];
    const float* pb1      = (const float*)d_in[17];
    const float* pW2      = (const float*)d_in[18];
    const float* pb2      = (const float*)d_in[19];
    const float* eW1      = (const float*)d_in[20];
    const float* eb1      = (const float*)d_in[21];
    const float* eW2      = (const float*)d_in[22];
    const float* eb2      = (const float*)d_in[23];
    const int*   neighbors= (const int*)d_in[24];

    float* out = (float*)d_out;
    float* out_vi = out;                          // [B,A,NCB]
    float* out_V  = out + (size_t)BB*AA*NCB;      // [B,A,N,NCB,3]

    cudaFuncSetAttribute(k_main, cudaFuncAttributeMaxDynamicSharedMemorySize,
                         (int)SMEM_BYTES);

    k_prep<<<7, 256>>>(fW1, fW2, f2oW, pW1, pW2, eW1, eW2);
    k_embed<<<BB*AA/4, 128>>>(xi, in2f_W);
    k_main<<<BB*AA/2, 512, SMEM_BYTES>>>(
        r_ij, cos_ij, f_ij, nmask,
        fb1, fb2, f2ob, aW1, ab1, aW2, ab2,
        pb1, pb2, eb1, eb2, neighbors, out_vi);
    k_assemble<<<BB*AA*NN, 128>>>(cos_ij, neighbors, out_V);
}

// round 6
// speedup vs baseline: 2.0563x; 1.0457x over previous
#include <cuda_runtime.h>
#include <cuda_fp16.h>
#include <math.h>
#include <stdint.h>

#define BB  4
#define AA  256
#define NN  64
#define NCB 128
#define NF  128
#define NSB 50

#define PITCH 136                        // fp16 elems per row
#define IMG_A (64 * PITCH * 2)           // 17408 B  (A/V images: 64 rows)
#define IMG_W (128 * PITCH * 2)          // 34816 B  (W images: 128 rows)
#define VPITCH 65

// ---------------- global scratch (no allocs allowed) ----------------
__device__ __align__(16) float d_y[BB*AA*NF];
__device__ __align__(16) float d_vij[(size_t)BB*AA*NN*NCB];
__device__ __align__(16) float d_Vik[BB*AA*NCB*3];
__device__ __align__(16) __half d_wsplit[7 * 2 * 128 * PITCH];

// ---------------- helpers ----------------
__device__ __forceinline__ void cp16(void* sdst, const void* gsrc) {
    unsigned s = (unsigned)__cvta_generic_to_shared(sdst);
    asm volatile("cp.async.cg.shared.global [%0], [%1], 16;" :: "r"(s), "l"(gsrc));
}
#define CP_COMMIT()  asm volatile("cp.async.commit_group;" ::: "memory")
#define CP_WAIT0()   asm volatile("cp.async.wait_group 0;" ::: "memory")

__device__ __forceinline__ void ldsm4(uint32_t* r, uint32_t saddr) {
    asm volatile("ldmatrix.sync.aligned.m8n8.x4.shared.b16 {%0,%1,%2,%3}, [%4];"
        : "=r"(r[0]), "=r"(r[1]), "=r"(r[2]), "=r"(r[3]) : "r"(saddr));
}
__device__ __forceinline__ void mma16816(float* c, const uint32_t* a,
                                         uint32_t b0, uint32_t b1) {
    asm volatile("mma.sync.aligned.m16n8k16.row.col.f32.f16.f16.f32 "
        "{%0,%1,%2,%3}, {%4,%5,%6,%7}, {%8,%9}, {%0,%1,%2,%3};"
        : "+f"(c[0]), "+f"(c[1]), "+f"(c[2]), "+f"(c[3])
        : "r"(a[0]), "r"(a[1]), "r"(a[2]), "r"(a[3]), "r"(b0), "r"(b1));
}
__device__ __forceinline__ float sspf(float x) {
    if (x > 15.f) return x - 0.69314718055994531f;
    return __logf(1.f + __expf(x)) - 0.69314718055994531f;
}
__device__ __forceinline__ void split2h(float v0, float v1, uint32_t& hi, uint32_t& lo) {
    __half h0 = __float2half_rn(v0);
    __half h1 = __float2half_rn(v1);
    float l0 = v0 - __half2float(h0);
    float l1 = v1 - __half2float(h1);
    __half2 hp; hp.x = h0; hp.y = h1;
    __half2 lp = __floats2half2_rn(l0, l1);
    hi = *reinterpret_cast<uint32_t*>(&hp);
    lo = *reinterpret_cast<uint32_t*>(&lp);
}

// ---------------- kernel: weight prep (blocks 0-6) + embedding (rest) -------
__global__ void __launch_bounds__(256) k_init(
    const float* fW1, const float* fW2, const float* f2oW,
    const float* pW1, const float* pW2, const float* eW1, const float* eW2,
    const float* __restrict__ xi, const float* __restrict__ in2f_W) {
    int bid = blockIdx.x;
    if (bid < 7) {
        const float* W; int K, realK;
        switch (bid) {
            case 0: W = fW1;  K = 64;  realK = NSB; break;
            case 1: W = fW2;  K = 128; realK = 128; break;
            case 2: W = f2oW; K = 128; realK = 128; break;
            case 3: W = pW1;  K = 128; realK = 128; break;
            case 4: W = pW2;  K = 128; realK = 128; break;
            case 5: W = eW1;  K = 128; realK = 128; break;
            default: W = eW2; K = 128; realK = 128; break;
        }
        __half* hi = d_wsplit + (size_t)bid * 2 * 128 * PITCH;
        __half* lo = hi + 128 * PITCH;
        for (int i = threadIdx.x; i < 128 * K; i += 256) {
            int n = i / K, k = i - (i / K) * K;
            float v = (k < realK) ? W[k * 128 + n] : 0.f;   // B^T: [n][k]
            __half h = __float2half_rn(v);
            hi[n * PITCH + k] = h;
            lo[n * PITCH + k] = __float2half_rn(v - __half2float(h));
        }
    } else {
        // embedding: 8 rows per block, 256 threads (2 groups x 128 cols)
        int row0 = (bid - 7) * 8;
        int c = threadIdx.x & 127, g = threadIdx.x >> 7;
        __shared__ float sx[8][128];
        #pragma unroll
        for (int j = 0; j < 4; j++)
            sx[g*4 + j][c] = xi[(size_t)(row0 + g*4 + j) * 128 + c];
        __syncthreads();
        float a0 = 0.f, a1 = 0.f, a2 = 0.f, a3 = 0.f;
        #pragma unroll 4
        for (int k = 0; k < 128; k++) {
            float w = __ldg(in2f_W + k * 128 + c);
            a0 = fmaf(sx[g*4+0][k], w, a0);
            a1 = fmaf(sx[g*4+1][k], w, a1);
            a2 = fmaf(sx[g*4+2][k], w, a2);
            a3 = fmaf(sx[g*4+3][k], w, a3);
        }
        d_y[(size_t)(row0 + g*4 + 0) * 128 + c] = a0;
        d_y[(size_t)(row0 + g*4 + 1) * 128 + c] = a1;
        d_y[(size_t)(row0 + g*4 + 2) * 128 + c] = a2;
        d_y[(size_t)(row0 + g*4 + 3) * 128 + c] = a3;
    }
}

// ---------------- SMEM byte layout (dynamic) ----------------
#define AH_OFF 0u
#define AL_OFF ((uint32_t)IMG_A)
#define VH_OFF ((uint32_t)(2*IMG_A))
#define VL_OFF ((uint32_t)(3*IMG_A))
#define WH_OFF ((uint32_t)(4*IMG_A))
#define WL_OFF ((uint32_t)(4*IMG_A + IMG_W))
#define SMEM_BYTES ((uint32_t)(4*IMG_A + 2*IMG_W))   // 139264

// split-fp16 GEMM: acc += A[64xK] @ W^T, warp tile m16 n32
template<int KSTEPS>
__device__ __forceinline__ void mm64(uint32_t aH, uint32_t wH,
                                     float acc[4][4],
                                     int warp_m, int warp_n, int lane) {
    const int rsel = lane & 15, hsel = lane >> 4;
    uint32_t aAddr = aH + (uint32_t)(((warp_m*16 + rsel) * PITCH + hsel*8) * 2);
    uint32_t wAddr = wH + (uint32_t)(((warp_n*32 + rsel) * PITCH + hsel*8) * 2);
    const uint32_t STEP16 = 16 * PITCH * 2;
    #pragma unroll 1
    for (int kk = 0; kk < KSTEPS; kk++) {
        uint32_t Ah[4], Al[4], Wh[2][4], Wl[2][4];
        uint32_t ak = aAddr + kk * 32;
        uint32_t wk = wAddr + kk * 32;
        ldsm4(Ah, ak);
        ldsm4(Al, ak + IMG_A);
        ldsm4(Wh[0], wk);
        ldsm4(Wh[1], wk + STEP16);
        ldsm4(Wl[0], wk + IMG_W);
        ldsm4(Wl[1], wk + IMG_W + STEP16);
        #pragma unroll
        for (int ng = 0; ng < 2; ng++)
            #pragma unroll
            for (int j = 0; j < 2; j++) {
                int nt = ng * 2 + j;
                mma16816(acc[nt], Ah, Wh[ng][j], Wh[ng][j+2]);
                mma16816(acc[nt], Ah, Wl[ng][j], Wl[ng][j+2]);
                mma16816(acc[nt], Al, Wh[ng][j], Wh[ng][j+2]);
            }
    }
}

// ---------------- kernel: fused interaction, 1 atom per CTA ----------------
__global__ void __launch_bounds__(512, 1) k_main(
    const float* __restrict__ r_ij, const float* __restrict__ cos_ij,
    const float* __restrict__ f_ij, const float* __restrict__ nmask,
    const float* __restrict__ fb1, const float* __restrict__ fb2,
    const float* __restrict__ f2ob,
    const float* __restrict__ aW1, const float* __restrict__ ab1,
    const float* __restrict__ aW2, const float* __restrict__ ab2,
    const float* __restrict__ pb1, const float* __restrict__ pb2,
    const float* __restrict__ eb1, const float* __restrict__ eb2,
    const int* __restrict__ neighbors, float* __restrict__ out_vi)
{
    extern __shared__ char smem[];
    const uint32_t sb = (uint32_t)__cvta_generic_to_shared(smem);
    const int tid = threadIdx.x, wid = tid >> 5, lane = tid & 31;
    const int warp_m = wid & 3, warp_n = wid >> 2;
    const int ba = blockIdx.x;
    const int b  = ba >> 8;

    __shared__ float sCut[64], sMask[64], cmS[64*3], vsumS[128], hidS[128];
    __shared__ float sBias[7][128];
    __shared__ int   sNbr[64];

    // prefetch stage-0 weights
    {
        const char* src = reinterpret_cast<const char*>(d_wsplit);
        for (int i = tid * 16; i < 2*IMG_W; i += 512*16)
            cp16(smem + WH_OFF + i, src + i);
        CP_COMMIT();
    }

    // biases to smem
    {
        const float* bp[7] = {fb1, fb2, f2ob, pb1, pb2, eb1, eb2};
        for (int i = tid; i < 7*128; i += 512)
            sBias[i >> 7][i & 127] = __ldg(bp[i >> 7] + (i & 127));
    }

    if (tid < 64) {
        int g = ba * NN + tid;
        float r = r_ij[g];
        sCut[tid]  = (r < 5.f) ? 0.5f * (__cosf(r * 0.62831853071795864f) + 1.f) : 0.f;
        float m = nmask[g];
        sMask[tid] = m;
        sNbr[tid]  = neighbors[g];
        cmS[tid*3+0] = cos_ij[(size_t)g*3+0] * m;
        cmS[tid*3+1] = cos_ij[(size_t)g*3+1] * m;
        cmS[tid*3+2] = cos_ij[(size_t)g*3+2] * m;
    }

    {   // zero A images
        uint64_t* z = reinterpret_cast<uint64_t*>(smem + AH_OFF);
        for (int i = tid; i < (2*IMG_A)/8; i += 512) z[i] = 0ull;
    }
    __syncthreads();
    {   // scatter split features
        const float* fg = f_ij + (size_t)ba * NN * NSB;
        __half* ah = reinterpret_cast<__half*>(smem + AH_OFF);
        __half* al = reinterpret_cast<__half*>(smem + AL_OFF);
        for (int i = tid; i < NN * NSB; i += 512) {
            int r = i / NSB, c = i - (i / NSB) * NSB;
            float v = fg[i];
            __half h = __float2half_rn(v);
            ah[r * PITCH + c] = h;
            al[r * PITCH + c] = __float2half_rn(v - __half2float(h));
        }
    }
    CP_WAIT0();
    __syncthreads();

    const int er  = lane >> 2;
    const int ec2 = (lane & 3) * 2;
    float* vikT = reinterpret_cast<float*>(smem + WH_OFF);   // [128][VPITCH]

    for (int s = 0; s < 7; s++) {
        const uint32_t aBase = sb + ((s == 3 || s == 5) ? VH_OFF : AH_OFF);
        float acc[4][4];
        #pragma unroll
        for (int nt = 0; nt < 4; nt++)
            #pragma unroll
            for (int j = 0; j < 4; j++) acc[nt][j] = 0.f;

        if (s == 0) mm64<4>(aBase, sb + WH_OFF, acc, warp_m, warp_n, lane);
        else        mm64<8>(aBase, sb + WH_OFF, acc, warp_m, warp_n, lane);

        __syncthreads();   // all warps done reading A and W

        if (s < 6) {       // prefetch next-stage weights (overlaps epilogue)
            const char* src = reinterpret_cast<const char*>(
                d_wsplit + (size_t)(s + 1) * 2 * 128 * PITCH);
            for (int i = tid * 16; i < 2*IMG_W; i += 512*16)
                cp16(smem + WH_OFF + i, src + i);
            CP_COMMIT();
        }

        // ---- epilogue (rows warp_m*16 + {er, er+8}) ----
        char* dstH = smem + ((s == 2) ? VH_OFF : AH_OFF);
        #pragma unroll
        for (int nt = 0; nt < 4; nt++) {
            int col = warp_n*32 + nt*8 + ec2;
            float b0 = sBias[s][col], b1 = sBias[s][col + 1];
            #pragma unroll
            for (int h = 0; h < 2; h++) {
                int row = warp_m*16 + er + h*8;
                float x0 = acc[nt][h*2+0] + b0;
                float x1 = acc[nt][h*2+1] + b1;
                if (s == 1) {
                    float cu = sCut[row];
                    const float2 y = *reinterpret_cast<const float2*>(
                        d_y + ((size_t)((b << 8) + sNbr[row]) << 7) + col);
                    x0 = x0 * cu * y.x;
                    x1 = x1 * cu * y.y;
                } else if (s == 4) {
                    *reinterpret_cast<float2*>(
                        d_vij + ((size_t)ba * 64 + row) * 128 + col) =
                        make_float2(x0, x1);
                    continue;
                } else if (s == 6) {
                    vikT[col * VPITCH + row]       = x0;
                    vikT[(col + 1) * VPITCH + row] = x1;
                    continue;
                } else {
                    x0 = sspf(x0); x1 = sspf(x1);
                }
                uint32_t hp, lp;
                split2h(x0, x1, hp, lp);
                uint32_t off = (uint32_t)(row * PITCH + col) * 2;
                *reinterpret_cast<uint32_t*>(dstH + off)         = hp;
                *reinterpret_cast<uint32_t*>(dstH + IMG_A + off) = lp;
            }
        }

        if (s < 6) CP_WAIT0();
        __syncthreads();
    }

    // ---- Vik[c][d] = sum_n vik[n][c] * cm[n][d] ----
    if (tid < 384) {
        int c = tid / 3, d = tid - 3 * (tid / 3);
        float s = 0.f;
        #pragma unroll 4
        for (int n = 0; n < 64; n++)
            s = fmaf(vikT[c * VPITCH + n], cmS[n * 3 + d], s);
        d_Vik[(size_t)ba * 384 + tid] = s;
    }

    // ---- vsum from V, atom MLP -> out_vi ----
    if (tid < 128) {
        const __half* vh = reinterpret_cast<const __half*>(smem + VH_OFF);
        const __half* vl = reinterpret_cast<const __half*>(smem + VL_OFF);
        float s = 0.f;
        #pragma unroll 4
        for (int n = 0; n < 64; n++) {
            float v = __half2float(vh[n * PITCH + tid]) + __half2float(vl[n * PITCH + tid]);
            s = fmaf(v, sMask[n], s);
        }
        vsumS[tid] = s;
    }
    __syncthreads();
    if (tid < 128) {
        float h = sBias[0][0];   // placeholder to keep reg alloc calm
        h = __ldg(ab1 + tid);
        #pragma unroll 4
        for (int k = 0; k < 128; k++)
            h = fmaf(vsumS[k], __ldg(aW1 + k * 128 + tid), h);
        hidS[tid] = sspf(h);
    }
    __syncthreads();
    if (tid < 128) {
        float o = __ldg(ab2 + tid);
        #pragma unroll 4
        for (int k = 0; k < 128; k++)
            o = fmaf(hidS[k], __ldg(aW2 + k * 128 + tid), o);
        out_vi[(size_t)ba * NF + tid] = o;
    }
}

// ---------------- kernel: assemble V (direct, float4) ----------------
__global__ void __launch_bounds__(96) k_assemble(
    const float* __restrict__ cos_ij,
    const int* __restrict__ neighbors,
    float* __restrict__ outV) {
    int idx = blockIdx.x;            // (b,a,n) flat
    int tid = threadIdx.x;           // 0..95
    int ba  = idx >> 6;
    int b   = idx >> 14;
    int nb  = __ldg(neighbors + idx);
    int e0  = tid * 4;
    int c0  = e0 / 3;

    float4 vl = *reinterpret_cast<const float4*>(d_Vik + (size_t)ba * 384 + e0);
    float4 vn = *reinterpret_cast<const float4*>(
        d_Vik + ((size_t)(b * AA + nb)) * 384 + e0);
    float cc[3];
    cc[0] = __ldg(cos_ij + (size_t)idx * 3 + 0);
    cc[1] = __ldg(cos_ij + (size_t)idx * 3 + 1);
    cc[2] = __ldg(cos_ij + (size_t)idx * 3 + 2);
    float vij0 = __ldg(d_vij + (size_t)idx * 128 + c0);
    float vij1 = __ldg(d_vij + (size_t)idx * 128 + c0 + 1);

    float vls[4] = {vl.x, vl.y, vl.z, vl.w};
    float vns[4] = {vn.x, vn.y, vn.z, vn.w};
    float4 o;
    float* op = reinterpret_cast<float*>(&o);
    #pragma unroll
    for (int j = 0; j < 4; j++) {
        int e = e0 + j;
        int c = e / 3, d = e - 3 * c;
        float vij = (c == c0) ? vij0 : vij1;
        op[j] = fmaf(vij, cc[d], vls[j] + vns[j]);
    }
    *reinterpret_cast<float4*>(outV + (size_t)idx * 384 + e0) = o;
}

// ---------------- launch ----------------
extern "C" void kernel_launch(void* const* d_in, const int* in_sizes, int n_in,
                              void* d_out, int out_size) {
    const float* xi       = (const float*)d_in[0];
    const float* r_ij     = (const float*)d_in[1];
    const float* cos_ij   = (const float*)d_in[2];
    const float* f_ij     = (const float*)d_in[3];
    const float* nmask    = (const float*)d_in[4];
    const float* fW1      = (const float*)d_in[5];
    const float* fb1      = (const float*)d_in[6];
    const float* fW2      = (const float*)d_in[7];
    const float* fb2      = (const float*)d_in[8];
    const float* in2f_W   = (const float*)d_in[9];
    const float* f2oW     = (const float*)d_in[10];
    const float* f2ob     = (const float*)d_in[11];
    const float* aW1      = (const float*)d_in[12];
    const float* ab1      = (const float*)d_in[13];
    const float* aW2      = (const float*)d_in[14];
    const float* ab2      = (const float*)d_in[15];
    const float* pW1      = (const float*)d_in[16];
    const float* pb1      = (const float*)d_in[17];
    const float* pW2      = (const float*)d_in[18];
    const float* pb2      = (const float*)d_in[19];
    const float* eW1      = (const float*)d_in[20];
    const float* eb1      = (const float*)d_in[21];
    const float* eW2      = (const float*)d_in[22];
    const float* eb2      = (const float*)d_in[23];
    const int*   neighbors= (const int*)d_in[24];

    float* out = (float*)d_out;
    float* out_vi = out;                          // [B,A,NCB]
    float* out_V  = out + (size_t)BB*AA*NCB;      // [B,A,N,NCB,3]

    cudaFuncSetAttribute(k_main, cudaFuncAttributeMaxDynamicSharedMemorySize,
                         (int)SMEM_BYTES);

    k_init<<<7 + BB*AA/8, 256>>>(fW1, fW2, f2oW, pW1, pW2, eW1, eW2, xi, in2f_W);
    k_main<<<BB*AA, 512, SMEM_BYTES>>>(
        r_ij, cos_ij, f_ij, nmask,
        fb1, fb2, f2ob, aW1, ab1, aW2, ab2,
        pb1, pb2, eb1, eb2, neighbors, out_vi);
    k_assemble<<<BB*AA*NN, 96>>>(cos_ij, neighbors, out_V);
}

// round 7
// speedup vs baseline: 2.1196x; 1.0308x over previous
#include <cuda_runtime.h>
#include <cuda_fp16.h>
#include <stdint.h>

#define BB  4
#define AA  256
#define NN  64
#define NCB 128
#define NF  128
#define NSB 50

#define PITCH 136
#define IMG_A (64 * PITCH * 2)          // 17408
#define IMG_W (128 * PITCH * 2)         // 34816
#define ATOM_BLK (4 * IMG_A)            // 69632 (Ah, Al, Vh, Vl)
#define W_OFF (2 * ATOM_BLK)            // 139264
#define SMEM_BYTES (W_OFF + 2 * IMG_W)  // 208896
#define VPITCH 65

// ---------------- global scratch ----------------
__device__ __align__(16) float d_y[BB*AA*NF];
__device__ __align__(16) float d_vij[(size_t)BB*AA*NN*NCB];
__device__ __align__(16) float d_Vik[BB*AA*NCB*3];
__device__ __align__(16) __half d_wsplit[7 * 2 * 128 * PITCH];

// ---------------- helpers ----------------
__device__ __forceinline__ void cp16(void* sdst, const void* gsrc) {
    unsigned s = (unsigned)__cvta_generic_to_shared(sdst);
    asm volatile("cp.async.cg.shared.global [%0], [%1], 16;" :: "r"(s), "l"(gsrc));
}
__device__ __forceinline__ void ldsm4(uint32_t* r, uint32_t saddr) {
    asm volatile("ldmatrix.sync.aligned.m8n8.x4.shared.b16 {%0,%1,%2,%3}, [%4];"
        : "=r"(r[0]), "=r"(r[1]), "=r"(r[2]), "=r"(r[3]) : "r"(saddr));
}
__device__ __forceinline__ void mma16816(float* c, const uint32_t* a,
                                         uint32_t b0, uint32_t b1) {
    asm volatile("mma.sync.aligned.m16n8k16.row.col.f32.f16.f16.f32 "
        "{%0,%1,%2,%3}, {%4,%5,%6,%7}, {%8,%9}, {%0,%1,%2,%3};"
        : "+f"(c[0]), "+f"(c[1]), "+f"(c[2]), "+f"(c[3])
        : "r"(a[0]), "r"(a[1]), "r"(a[2]), "r"(a[3]), "r"(b0), "r"(b1));
}
__device__ __forceinline__ float sspf(float x) {
    if (x > 15.f) return x - 0.69314718055994531f;
    return __logf(1.f + __expf(x)) - 0.69314718055994531f;
}
__device__ __forceinline__ void split2h(float v0, float v1, uint32_t& hi, uint32_t& lo) {
    __half h0 = __float2half_rn(v0);
    __half h1 = __float2half_rn(v1);
    float l0 = v0 - __half2float(h0);
    float l1 = v1 - __half2float(h1);
    __half2 hp; hp.x = h0; hp.y = h1;
    __half2 lp = __floats2half2_rn(l0, l1);
    hi = *reinterpret_cast<uint32_t*>(&hp);
    lo = *reinterpret_cast<uint32_t*>(&lp);
}
__device__ __forceinline__ uint32_t smem_u32(const void* p) {
    return (uint32_t)__cvta_generic_to_shared(p);
}
__device__ __forceinline__ void mbar_wait(uint32_t mb, uint32_t parity) {
    uint32_t done;
    asm volatile("{\n\t.reg .pred p;\n\t"
        "mbarrier.try_wait.parity.acquire.cta.shared::cta.b64 p, [%1], %2;\n\t"
        "selp.b32 %0, 1, 0, p;\n\t}"
        : "=r"(done) : "r"(mb), "r"(parity) : "memory");
    if (!done) {
        asm volatile("{\n\t.reg .pred P1;\n\t"
            "W_%=:\n\t"
            "mbarrier.try_wait.parity.acquire.cta.shared::cta.b64 P1, [%0], %1, 0x989680;\n\t"
            "@P1 bra.uni D_%=;\n\t"
            "bra.uni W_%=;\n\t"
            "D_%=:\n\t}"
            :: "r"(mb), "r"(parity) : "memory");
    }
}

// ---------------- kernel: weight prep + embedding ----------------
__global__ void __launch_bounds__(256) k_init(
    const float* fW1, const float* fW2, const float* f2oW,
    const float* pW1, const float* pW2, const float* eW1, const float* eW2,
    const float* __restrict__ xi, const float* __restrict__ in2f_W) {
    int bid = blockIdx.x;
    if (bid < 7) {
        const float* W; int K, realK;
        switch (bid) {
            case 0: W = fW1;  K = 64;  realK = NSB; break;
            case 1: W = fW2;  K = 128; realK = 128; break;
            case 2: W = f2oW; K = 128; realK = 128; break;
            case 3: W = pW1;  K = 128; realK = 128; break;
            case 4: W = pW2;  K = 128; realK = 128; break;
            case 5: W = eW1;  K = 128; realK = 128; break;
            default: W = eW2; K = 128; realK = 128; break;
        }
        __half* hi = d_wsplit + (size_t)bid * 2 * 128 * PITCH;
        __half* lo = hi + 128 * PITCH;
        for (int i = threadIdx.x; i < 128 * K; i += 256) {
            int n = i / K, k = i - (i / K) * K;
            float v = (k < realK) ? W[k * 128 + n] : 0.f;   // B^T: [n][k]
            __half h = __float2half_rn(v);
            hi[n * PITCH + k] = h;
            lo[n * PITCH + k] = __float2half_rn(v - __half2float(h));
        }
    } else {
        // embedding: 4 rows per block, 2 groups x 128 cols
        int row0 = (bid - 7) * 4;
        int c = threadIdx.x & 127, g = threadIdx.x >> 7;
        __shared__ float sx[4][128];
        sx[g*2 + 0][c] = xi[(size_t)(row0 + g*2 + 0) * 128 + c];
        sx[g*2 + 1][c] = xi[(size_t)(row0 + g*2 + 1) * 128 + c];
        __syncthreads();
        float a0 = 0.f, a1 = 0.f;
        #pragma unroll 8
        for (int k = 0; k < 128; k++) {
            float w = __ldg(in2f_W + k * 128 + c);
            a0 = fmaf(sx[g*2+0][k], w, a0);
            a1 = fmaf(sx[g*2+1][k], w, a1);
        }
        d_y[(size_t)(row0 + g*2 + 0) * 128 + c] = a0;
        d_y[(size_t)(row0 + g*2 + 1) * 128 + c] = a1;
    }
}

// split-fp16 GEMM: acc += A[64xK] @ W^T[128xK], 8 warps per pipeline,
// warp tile m16 x n64
template<int KSTEPS>
__device__ __forceinline__ void mm(uint32_t aBase, uint32_t wBase,
                                   float (&acc)[8][4], int lw, int lane) {
    const int warp_m = lw & 3, warp_h = lw >> 2;
    const int rsel = lane & 15, hsel = lane >> 4;
    uint32_t aAddr = aBase + (uint32_t)(((warp_m*16 + rsel) * PITCH + hsel*8) * 2);
    uint32_t wAddr = wBase + (uint32_t)(((warp_h*64 + rsel) * PITCH + hsel*8) * 2);
    const uint32_t STEP16 = 16 * PITCH * 2;
    #pragma unroll 1
    for (int kk = 0; kk < KSTEPS; kk++) {
        uint32_t Ah[4], Al[4], Wh[4][4], Wl[4][4];
        uint32_t ak = aAddr + kk * 32;
        uint32_t wk = wAddr + kk * 32;
        ldsm4(Ah, ak);
        ldsm4(Al, ak + IMG_A);
        #pragma unroll
        for (int q = 0; q < 4; q++) {
            ldsm4(Wh[q], wk + q * STEP16);
            ldsm4(Wl[q], wk + q * STEP16 + IMG_W);
        }
        #pragma unroll
        for (int q = 0; q < 4; q++)
            #pragma unroll
            for (int j = 0; j < 2; j++) {
                int nt = q * 2 + j;
                mma16816(acc[nt], Ah, Wh[q][j], Wh[q][j+2]);
                mma16816(acc[nt], Ah, Wl[q][j], Wl[q][j+2]);
                mma16816(acc[nt], Al, Wh[q][j], Wh[q][j+2]);
            }
    }
}

// stage epilogue for one pipeline
__device__ __forceinline__ void epilogue(
    int s, float (&acc)[8][4], char* smem, int pid, int ba0,
    int lw, int lane, const float (*sBias)[128],
    const float* sCut, const int* sNbr)
{
    const int warp_m = lw & 3, warp_h = lw >> 2;
    const int er = lane >> 2, ec2 = (lane & 3) * 2;
    char* atomBase = smem + pid * ATOM_BLK;
    char* dstH = atomBase + ((s == 2) ? 2*IMG_A : 0);
    float* vikT = reinterpret_cast<float*>(smem + W_OFF + pid * IMG_W);
    const int baG = ba0 + pid;
    const int bA = baG >> 8;
    #pragma unroll
    for (int nt = 0; nt < 8; nt++) {
        int col = warp_h*64 + nt*8 + ec2;
        float b0 = sBias[s][col], b1 = sBias[s][col + 1];
        #pragma unroll
        for (int h = 0; h < 2; h++) {
            int row = warp_m*16 + er + h*8;        // 0..63
            int grow = pid*64 + row;
            float x0 = acc[nt][h*2+0] + b0;
            float x1 = acc[nt][h*2+1] + b1;
            if (s == 1) {
                float cu = sCut[grow];
                const float2 y = *reinterpret_cast<const float2*>(
                    d_y + ((size_t)((bA << 8) + sNbr[grow]) << 7) + col);
                x0 = x0 * cu * y.x;
                x1 = x1 * cu * y.y;
            } else if (s == 4) {
                *reinterpret_cast<float2*>(
                    d_vij + ((size_t)baG * 64 + row) * 128 + col) =
                    make_float2(x0, x1);
                continue;
            } else if (s == 6) {
                vikT[col * VPITCH + row]       = x0;
                vikT[(col + 1) * VPITCH + row] = x1;
                continue;
            } else {
                x0 = sspf(x0); x1 = sspf(x1);
            }
            uint32_t hp, lp;
            split2h(x0, x1, hp, lp);
            uint32_t off = (uint32_t)(row * PITCH + col) * 2;
            *reinterpret_cast<uint32_t*>(dstH + off)         = hp;
            *reinterpret_cast<uint32_t*>(dstH + IMG_A + off) = lp;
        }
    }
}

// ---------------- kernel: fused interaction, 2 staggered pipelines ---------
__global__ void __launch_bounds__(512, 1) k_main(
    const float* __restrict__ r_ij, const float* __restrict__ cos_ij,
    const float* __restrict__ f_ij, const float* __restrict__ nmask,
    const float* __restrict__ fb1, const float* __restrict__ fb2,
    const float* __restrict__ f2ob,
    const float* __restrict__ aW1, const float* __restrict__ ab1,
    const float* __restrict__ aW2, const float* __restrict__ ab2,
    const float* __restrict__ pb1, const float* __restrict__ pb2,
    const float* __restrict__ eb1, const float* __restrict__ eb2,
    const int* __restrict__ neighbors, float* __restrict__ out_vi)
{
    extern __shared__ char smem[];
    const uint32_t sb = smem_u32(smem);
    const int tid = threadIdx.x;
    const int pid = tid >> 8;            // pipeline/atom: 0 or 1
    const int lt  = tid & 255, lw = lt >> 5, lane = tid & 31;
    const int ba0 = blockIdx.x * 2;

    __shared__ float sCut[128], sMask[128], cmS[384], vsumS[256], hidS[256];
    __shared__ float sBias[7][128];
    __shared__ int   sNbr[128];
    __shared__ __align__(8) uint64_t mbarW;
    const uint32_t mbar = smem_u32(&mbarW);

    if (tid == 0)
        asm volatile("mbarrier.init.shared.b64 [%0], %1;"
                     :: "r"(mbar), "r"(512u) : "memory");

    {   // biases to smem
        const float* bp[7] = {fb1, fb2, f2ob, pb1, pb2, eb1, eb2};
        for (int i = tid; i < 7*128; i += 512)
            sBias[i >> 7][i & 127] = __ldg(bp[i >> 7] + (i & 127));
    }
    if (tid < 128) {
        int g = ba0 * NN + tid;
        float r = r_ij[g];
        sCut[tid]  = (r < 5.f) ? 0.5f * (__cosf(r * 0.62831853071795864f) + 1.f) : 0.f;
        float m = nmask[g];
        sMask[tid] = m;
        sNbr[tid]  = neighbors[g];
        cmS[tid*3+0] = cos_ij[(size_t)g*3+0] * m;
        cmS[tid*3+1] = cos_ij[(size_t)g*3+1] * m;
        cmS[tid*3+2] = cos_ij[(size_t)g*3+2] * m;
    }
    {   // zero both atoms' A images
        uint64_t* z0 = reinterpret_cast<uint64_t*>(smem);
        uint64_t* z1 = reinterpret_cast<uint64_t*>(smem + ATOM_BLK);
        for (int i = tid; i < (2*IMG_A)/8; i += 512) { z0[i] = 0ull; z1[i] = 0ull; }
    }
    __syncthreads();   // mbar init + zero visible

    {   // issue W(0) + mbarrier arrive-on-completion
        const char* src = reinterpret_cast<const char*>(d_wsplit);
        for (int i = tid * 16; i < 2*IMG_W; i += 512*16)
            cp16(smem + W_OFF + i, src + i);
        asm volatile("cp.async.mbarrier.arrive.noinc.shared.b64 [%0];"
                     :: "r"(mbar) : "memory");
    }
    {   // scatter split features (each pipeline its own atom)
        const float* fg = f_ij + (size_t)(ba0 + pid) * NN * NSB;
        __half* ah = reinterpret_cast<__half*>(smem + pid * ATOM_BLK);
        __half* al = reinterpret_cast<__half*>(smem + pid * ATOM_BLK + IMG_A);
        for (int i = lt; i < NN * NSB; i += 256) {
            int r = i / NSB, c = i - (i / NSB) * NSB;
            float v = fg[i];
            __half h = __float2half_rn(v);
            ah[r * PITCH + c] = h;
            al[r * PITCH + c] = __float2half_rn(v - __half2float(h));
        }
    }
    __syncthreads();   // feature images ready

    float acc[8][4];

    for (int s = 0; s < 7; s++) {
        // Q: epilogue of previous stage overlaps P's MMAs
        if (pid == 1 && s > 0) {
            epilogue(s - 1, acc, smem, 1, ba0, lw, lane, sBias, sCut, sNbr);
            asm volatile("bar.sync 2, 256;" ::: "memory");   // Q-internal
        }
        #pragma unroll
        for (int nt = 0; nt < 8; nt++)
            #pragma unroll
            for (int j = 0; j < 4; j++) acc[nt][j] = 0.f;

        mbar_wait(mbar, (uint32_t)(s & 1));   // W(s) fully arrived

        uint32_t aBase = sb + pid * ATOM_BLK + ((s == 3 || s == 5) ? 2*IMG_A : 0);
        if (s == 0) mm<4>(aBase, sb + W_OFF, acc, lw, lane);
        else        mm<8>(aBase, sb + W_OFF, acc, lw, lane);

        // P: epilogue overlaps Q's MMAs (deferred for s==6: target is W buffer)
        if (pid == 0 && s < 6)
            epilogue(s, acc, smem, 0, ba0, lw, lane, sBias, sCut, sNbr);

        __syncthreads();   // all done reading W(s); P images consistent

        if (s < 6) {       // issue W(s+1); wait happens next window after Q.epi
            const char* src = reinterpret_cast<const char*>(
                d_wsplit + (size_t)(s + 1) * 2 * 128 * PITCH);
            for (int i = tid * 16; i < 2*IMG_W; i += 512*16)
                cp16(smem + W_OFF + i, src + i);
            asm volatile("cp.async.mbarrier.arrive.noinc.shared.b64 [%0];"
                         :: "r"(mbar) : "memory");
        }
    }

    // stage-6 epilogues (both pipelines) -> vikT in W buffer
    epilogue(6, acc, smem, pid, ba0, lw, lane, sBias, sCut, sNbr);
    __syncthreads();

    // ---- Vik[c][d] = sum_n vik[n][c] * cm[n][d] (both atoms) ----
    for (int e = tid; e < 768; e += 512) {
        int atom = e / 384, rem = e - atom * 384;
        int c = rem / 3, d = rem - 3 * (rem / 3);
        const float* vikT = reinterpret_cast<const float*>(smem + W_OFF + atom * IMG_W);
        float s = 0.f;
        #pragma unroll 4
        for (int n = 0; n < 64; n++)
            s = fmaf(vikT[c * VPITCH + n], cmS[(atom*64 + n) * 3 + d], s);
        d_Vik[(size_t)(ba0 + atom) * 384 + rem] = s;
    }

    // ---- vsum from V, atom MLP -> out_vi ----
    if (tid < 256) {
        int atom = tid >> 7, c = tid & 127;
        const __half* vh = reinterpret_cast<const __half*>(smem + atom*ATOM_BLK + 2*IMG_A);
        const __half* vl = reinterpret_cast<const __half*>(smem + atom*ATOM_BLK + 3*IMG_A);
        float s = 0.f;
        #pragma unroll 4
        for (int n = 0; n < 64; n++) {
            float v = __half2float(vh[n * PITCH + c]) + __half2float(vl[n * PITCH + c]);
            s = fmaf(v, sMask[atom*64 + n], s);
        }
        vsumS[tid] = s;
    }
    __syncthreads();
    if (tid < 256) {
        int atom = tid >> 7, c = tid & 127;
        float h = __ldg(ab1 + c);
        #pragma unroll 4
        for (int k = 0; k < 128; k++)
            h = fmaf(vsumS[atom*128 + k], __ldg(aW1 + k * 128 + c), h);
        hidS[tid] = sspf(h);
    }
    __syncthreads();
    if (tid < 256) {
        int atom = tid >> 7, c = tid & 127;
        float o = __ldg(ab2 + c);
        #pragma unroll 4
        for (int k = 0; k < 128; k++)
            o = fmaf(hidS[atom*128 + k], __ldg(aW2 + k * 128 + c), o);
        out_vi[(size_t)(ba0 + atom) * NF + c] = o;
    }
}

// ---------------- kernel: assemble V (direct, float4) ----------------
__global__ void __launch_bounds__(96) k_assemble(
    const float* __restrict__ cos_ij,
    const int* __restrict__ neighbors,
    float* __restrict__ outV) {
    int idx = blockIdx.x;            // (b,a,n) flat
    int tid = threadIdx.x;           // 0..95
    int ba  = idx >> 6;
    int b   = idx >> 14;
    int nb  = __ldg(neighbors + idx);
    int e0  = tid * 4;
    int c0  = e0 / 3;

    float4 vl = *reinterpret_cast<const float4*>(d_Vik + (size_t)ba * 384 + e0);
    float4 vn = *reinterpret_cast<const float4*>(
        d_Vik + ((size_t)(b * AA + nb)) * 384 + e0);
    float cc[3];
    cc[0] = __ldg(cos_ij + (size_t)idx * 3 + 0);
    cc[1] = __ldg(cos_ij + (size_t)idx * 3 + 1);
    cc[2] = __ldg(cos_ij + (size_t)idx * 3 + 2);
    float vij0 = __ldg(d_vij + (size_t)idx * 128 + c0);
    float vij1 = __ldg(d_vij + (size_t)idx * 128 + c0 + 1);

    float vls[4] = {vl.x, vl.y, vl.z, vl.w};
    float vns[4] = {vn.x, vn.y, vn.z, vn.w};
    float4 o;
    float* op = reinterpret_cast<float*>(&o);
    #pragma unroll
    for (int j = 0; j < 4; j++) {
        int e = e0 + j;
        int c = e / 3, d = e - 3 * c;
        float vij = (c == c0) ? vij0 : vij1;
        op[j] = fmaf(vij, cc[d], vls[j] + vns[j]);
    }
    *reinterpret_cast<float4*>(outV + (size_t)idx * 384 + e0) = o;
}

// ---------------- launch ----------------
extern "C" void kernel_launch(void* const* d_in, const int* in_sizes, int n_in,
                              void* d_out, int out_size) {
    const float* xi       = (const float*)d_in[0];
    const float* r_ij     = (const float*)d_in[1];
    const float* cos_ij   = (const float*)d_in[2];
    const float* f_ij     = (const float*)d_in[3];
    const float* nmask    = (const float*)d_in[4];
    const float* fW1      = (const float*)d_in[5];
    const float* fb1      = (const float*)d_in[6];
    const float* fW2      = (const float*)d_in[7];
    const float* fb2      = (const float*)d_in[8];
    const float* in2f_W   = (const float*)d_in[9];
    const float* f2oW     = (const float*)d_in[10];
    const float* f2ob     = (const float*)d_in[11];
    const float* aW1      = (const float*)d_in[12];
    const float* ab1      = (const float*)d_in[13];
    const float* aW2      = (const float*)d_in[14];
    const float* ab2      = (const float*)d_in[15];
    const float* pW1      = (const float*)d_in[16];
    const float* pb1      = (const float*)d_in[17];
    const float* pW2      = (const float*)d_in[18];
    const float* pb2      = (const float*)d_in[19];
    const float* eW1      = (const float*)d_in[20];
    const float* eb1      = (const float*)d_in[21];
    const float* eW2      = (const float*)d_in[22];
    const float* eb2      = (const float*)d_in[23];
    const int*   neighbors= (const int*)d_in[24];

    float* out = (float*)d_out;
    float* out_vi = out;                          // [B,A,NCB]
    float* out_V  = out + (size_t)BB*AA*NCB;      // [B,A,N,NCB,3]

    cudaFuncSetAttribute(k_main, cudaFuncAttributeMaxDynamicSharedMemorySize,
                         (int)SMEM_BYTES);

    k_init<<<7 + BB*AA/4, 256>>>(fW1, fW2, f2oW, pW1, pW2, eW1, eW2, xi, in2f_W);
    k_main<<<BB*AA/2, 512, SMEM_BYTES>>>(
        r_ij, cos_ij, f_ij, nmask,
        fb1, fb2, f2ob, aW1, ab1, aW2, ab2,
        pb1, pb2, eb1, eb2, neighbors, out_vi);
    k_assemble<<<BB*AA*NN, 96>>>(cos_ij, neighbors, out_V);
}

// round 8
// speedup vs baseline: 2.1370x; 1.0082x over previous
#include <cuda_runtime.h>
#include <cuda_fp16.h>
#include <stdint.h>

#define BB  4
#define AA  256
#define NN  64
#define NCB 128
#define NF  128
#define NSB 50

#define PITCH 136
#define IMG_A (64 * PITCH * 2)          // 17408
#define IMG_W (128 * PITCH * 2)         // 34816
#define ATOM_BLK (4 * IMG_A)            // 69632 (Ah, Al, Vh, Vl)
#define W_OFF (2 * ATOM_BLK)            // 139264
#define SMEM_BYTES (W_OFF + 2 * IMG_W)  // 208896
#define VPITCH 65

// ---------------- global scratch ----------------
__device__ __align__(16) float d_y[BB*AA*NF];
__device__ __align__(16) float d_vij[(size_t)BB*AA*NN*NCB];
__device__ __align__(16) float d_Vik[BB*AA*NCB*3];
__device__ __align__(16) __half d_wsplit[7 * 2 * 128 * PITCH];

// ---------------- helpers ----------------
__device__ __forceinline__ void cp16(void* sdst, const void* gsrc) {
    unsigned s = (unsigned)__cvta_generic_to_shared(sdst);
    asm volatile("cp.async.cg.shared.global [%0], [%1], 16;" :: "r"(s), "l"(gsrc));
}
__device__ __forceinline__ void ldsm4(uint32_t* r, uint32_t saddr) {
    asm volatile("ldmatrix.sync.aligned.m8n8.x4.shared.b16 {%0,%1,%2,%3}, [%4];"
        : "=r"(r[0]), "=r"(r[1]), "=r"(r[2]), "=r"(r[3]) : "r"(saddr));
}
__device__ __forceinline__ void mma16816(float* c, const uint32_t* a,
                                         uint32_t b0, uint32_t b1) {
    asm volatile("mma.sync.aligned.m16n8k16.row.col.f32.f16.f16.f32 "
        "{%0,%1,%2,%3}, {%4,%5,%6,%7}, {%8,%9}, {%0,%1,%2,%3};"
        : "+f"(c[0]), "+f"(c[1]), "+f"(c[2]), "+f"(c[3])
        : "r"(a[0]), "r"(a[1]), "r"(a[2]), "r"(a[3]), "r"(b0), "r"(b1));
}
// f16-accumulator variant: D/C are 2 b32 regs holding 4 halves
__device__ __forceinline__ void mma16816h(uint32_t* c, const uint32_t* a,
                                          uint32_t b0, uint32_t b1) {
    asm volatile("mma.sync.aligned.m16n8k16.row.col.f16.f16.f16.f16 "
        "{%0,%1}, {%2,%3,%4,%5}, {%6,%7}, {%0,%1};"
        : "+r"(c[0]), "+r"(c[1])
        : "r"(a[0]), "r"(a[1]), "r"(a[2]), "r"(a[3]), "r"(b0), "r"(b1));
}
__device__ __forceinline__ float sspf(float x) {
    if (x > 15.f) return x - 0.69314718055994531f;
    return __logf(1.f + __expf(x)) - 0.69314718055994531f;
}
__device__ __forceinline__ void split2h(float v0, float v1, uint32_t& hi, uint32_t& lo) {
    __half h0 = __float2half_rn(v0);
    __half h1 = __float2half_rn(v1);
    float l0 = v0 - __half2float(h0);
    float l1 = v1 - __half2float(h1);
    __half2 hp; hp.x = h0; hp.y = h1;
    __half2 lp = __floats2half2_rn(l0, l1);
    hi = *reinterpret_cast<uint32_t*>(&hp);
    lo = *reinterpret_cast<uint32_t*>(&lp);
}
__device__ __forceinline__ uint32_t smem_u32(const void* p) {
    return (uint32_t)__cvta_generic_to_shared(p);
}
__device__ __forceinline__ void mbar_wait(uint32_t mb, uint32_t parity) {
    uint32_t done;
    asm volatile("{\n\t.reg .pred p;\n\t"
        "mbarrier.try_wait.parity.acquire.cta.shared::cta.b64 p, [%1], %2;\n\t"
        "selp.b32 %0, 1, 0, p;\n\t}"
        : "=r"(done) : "r"(mb), "r"(parity) : "memory");
    if (!done) {
        asm volatile("{\n\t.reg .pred P1;\n\t"
            "W_%=:\n\t"
            "mbarrier.try_wait.parity.acquire.cta.shared::cta.b64 P1, [%0], %1, 0x989680;\n\t"
            "@P1 bra.uni D_%=;\n\t"
            "bra.uni W_%=;\n\t"
            "D_%=:\n\t}"
            :: "r"(mb), "r"(parity) : "memory");
    }
}

// ---------------- kernel: weight prep + embedding ----------------
__global__ void __launch_bounds__(256) k_init(
    const float* fW1, const float* fW2, const float* f2oW,
    const float* pW1, const float* pW2, const float* eW1, const float* eW2,
    const float* __restrict__ xi, const float* __restrict__ in2f_W) {
    int bid = blockIdx.x;
    if (bid < 7) {
        const float* W; int K, realK;
        switch (bid) {
            case 0: W = fW1;  K = 64;  realK = NSB; break;
            case 1: W = fW2;  K = 128; realK = 128; break;
            case 2: W = f2oW; K = 128; realK = 128; break;
            case 3: W = pW1;  K = 128; realK = 128; break;
            case 4: W = pW2;  K = 128; realK = 128; break;
            case 5: W = eW1;  K = 128; realK = 128; break;
            default: W = eW2; K = 128; realK = 128; break;
        }
        __half* hi = d_wsplit + (size_t)bid * 2 * 128 * PITCH;
        __half* lo = hi + 128 * PITCH;
        for (int i = threadIdx.x; i < 128 * K; i += 256) {
            int n = i / K, k = i - (i / K) * K;
            float v = (k < realK) ? W[k * 128 + n] : 0.f;   // B^T: [n][k]
            __half h = __float2half_rn(v);
            hi[n * PITCH + k] = h;
            lo[n * PITCH + k] = __float2half_rn(v - __half2float(h));
        }
    } else {
        // embedding: 2 rows per block (grid-parallel, latency-hiding)
        int row0 = (bid - 7) * 2;
        int c = threadIdx.x & 127, g = threadIdx.x >> 7;
        __shared__ float sx[2][128];
        sx[g][c] = xi[(size_t)(row0 + g) * 128 + c];
        __syncthreads();
        float a0 = 0.f;
        #pragma unroll 8
        for (int k = 0; k < 128; k++)
            a0 = fmaf(sx[g][k], __ldg(in2f_W + k * 128 + c), a0);
        d_y[(size_t)(row0 + g) * 128 + c] = a0;
    }
}

// split-fp16 GEMM: hi*hi in f32 acc, cross terms in f16 acc (2x rate if HW allows)
template<int KSTEPS>
__device__ __forceinline__ void mm(uint32_t aBase, uint32_t wBase,
                                   float (&acc)[8][4], uint32_t (&accL)[8][2],
                                   int lw, int lane) {
    const int warp_m = lw & 3, warp_h = lw >> 2;
    const int rsel = lane & 15, hsel = lane >> 4;
    uint32_t aAddr = aBase + (uint32_t)(((warp_m*16 + rsel) * PITCH + hsel*8) * 2);
    uint32_t wAddr = wBase + (uint32_t)(((warp_h*64 + rsel) * PITCH + hsel*8) * 2);
    const uint32_t STEP16 = 16 * PITCH * 2;
    #pragma unroll 1
    for (int kk = 0; kk < KSTEPS; kk++) {
        uint32_t Ah[4], Al[4], Wh[4][4], Wl[4][4];
        uint32_t ak = aAddr + kk * 32;
        uint32_t wk = wAddr + kk * 32;
        ldsm4(Ah, ak);
        ldsm4(Al, ak + IMG_A);
        #pragma unroll
        for (int q = 0; q < 4; q++) {
            ldsm4(Wh[q], wk + q * STEP16);
            ldsm4(Wl[q], wk + q * STEP16 + IMG_W);
        }
        #pragma unroll
        for (int q = 0; q < 4; q++)
            #pragma unroll
            for (int j = 0; j < 2; j++) {
                int nt = q * 2 + j;
                mma16816(acc[nt], Ah, Wh[q][j], Wh[q][j+2]);       // hi*hi -> f32
                mma16816h(accL[nt], Ah, Wl[q][j], Wl[q][j+2]);     // hi*lo -> f16
                mma16816h(accL[nt], Al, Wh[q][j], Wh[q][j+2]);     // lo*hi -> f16
            }
    }
}

// stage epilogue for one pipeline
__device__ __forceinline__ void epilogue(
    int s, float (&acc)[8][4], uint32_t (&accL)[8][2], char* smem, int pid, int ba0,
    int lw, int lane, const float (*sBias)[128],
    const float* sCut, const int* sNbr)
{
    const int warp_m = lw & 3, warp_h = lw >> 2;
    const int er = lane >> 2, ec2 = (lane & 3) * 2;
    char* atomBase = smem + pid * ATOM_BLK;
    char* dstH = atomBase + ((s == 2) ? 2*IMG_A : 0);
    float* vikT = reinterpret_cast<float*>(smem + W_OFF + pid * IMG_W);
    const int baG = ba0 + pid;
    const int bA = baG >> 8;
    #pragma unroll
    for (int nt = 0; nt < 8; nt++) {
        int col = warp_h*64 + nt*8 + ec2;
        float b0 = sBias[s][col], b1 = sBias[s][col + 1];
        #pragma unroll
        for (int h = 0; h < 2; h++) {
            int row = warp_m*16 + er + h*8;        // 0..63
            int grow = pid*64 + row;
            __half2 lo2 = *reinterpret_cast<__half2*>(&accL[nt][h]);
            float x0 = acc[nt][h*2+0] + __half2float(lo2.x) + b0;
            float x1 = acc[nt][h*2+1] + __half2float(lo2.y) + b1;
            if (s == 1) {
                float cu = sCut[grow];
                const float2 y = *reinterpret_cast<const float2*>(
                    d_y + ((size_t)((bA << 8) + sNbr[grow]) << 7) + col);
                x0 = x0 * cu * y.x;
                x1 = x1 * cu * y.y;
            } else if (s == 4) {
                *reinterpret_cast<float2*>(
                    d_vij + ((size_t)baG * 64 + row) * 128 + col) =
                    make_float2(x0, x1);
                continue;
            } else if (s == 6) {
                vikT[col * VPITCH + row]       = x0;
                vikT[(col + 1) * VPITCH + row] = x1;
                continue;
            } else {
                x0 = sspf(x0); x1 = sspf(x1);
            }
            uint32_t hp, lp;
            split2h(x0, x1, hp, lp);
            uint32_t off = (uint32_t)(row * PITCH + col) * 2;
            *reinterpret_cast<uint32_t*>(dstH + off)         = hp;
            *reinterpret_cast<uint32_t*>(dstH + IMG_A + off) = lp;
        }
    }
}

// ---------------- kernel: fused interaction, 2 staggered pipelines ---------
__global__ void __launch_bounds__(512, 1) k_main(
    const float* __restrict__ r_ij, const float* __restrict__ cos_ij,
    const float* __restrict__ f_ij, const float* __restrict__ nmask,
    const float* __restrict__ fb1, const float* __restrict__ fb2,
    const float* __restrict__ f2ob,
    const float* __restrict__ aW1, const float* __restrict__ ab1,
    const float* __restrict__ aW2, const float* __restrict__ ab2,
    const float* __restrict__ pb1, const float* __restrict__ pb2,
    const float* __restrict__ eb1, const float* __restrict__ eb2,
    const int* __restrict__ neighbors, float* __restrict__ out_vi)
{
    extern __shared__ char smem[];
    const uint32_t sb = smem_u32(smem);
    const int tid = threadIdx.x;
    const int pid = tid >> 8;            // pipeline/atom: 0 or 1
    const int lt  = tid & 255, lw = lt >> 5, lane = tid & 31;
    const int ba0 = blockIdx.x * 2;

    __shared__ float sCut[128], sMask[128], cmS[384], vsumS[256], hidS[256];
    __shared__ float sBias[7][128];
    __shared__ int   sNbr[128];
    __shared__ __align__(8) uint64_t mbarW;
    const uint32_t mbar = smem_u32(&mbarW);

    if (tid == 0)
        asm volatile("mbarrier.init.shared.b64 [%0], %1;"
                     :: "r"(mbar), "r"(512u) : "memory");

    {   // biases to smem
        const float* bp[7] = {fb1, fb2, f2ob, pb1, pb2, eb1, eb2};
        for (int i = tid; i < 7*128; i += 512)
            sBias[i >> 7][i & 127] = __ldg(bp[i >> 7] + (i & 127));
    }
    if (tid < 128) {
        int g = ba0 * NN + tid;
        float r = r_ij[g];
        sCut[tid]  = (r < 5.f) ? 0.5f * (__cosf(r * 0.62831853071795864f) + 1.f) : 0.f;
        float m = nmask[g];
        sMask[tid] = m;
        sNbr[tid]  = neighbors[g];
        cmS[tid*3+0] = cos_ij[(size_t)g*3+0] * m;
        cmS[tid*3+1] = cos_ij[(size_t)g*3+1] * m;
        cmS[tid*3+2] = cos_ij[(size_t)g*3+2] * m;
    }
    {   // zero both atoms' A images
        uint64_t* z0 = reinterpret_cast<uint64_t*>(smem);
        uint64_t* z1 = reinterpret_cast<uint64_t*>(smem + ATOM_BLK);
        for (int i = tid; i < (2*IMG_A)/8; i += 512) { z0[i] = 0ull; z1[i] = 0ull; }
    }
    __syncthreads();   // mbar init + zero visible

    {   // issue W(0) + mbarrier arrive-on-completion
        const char* src = reinterpret_cast<const char*>(d_wsplit);
        for (int i = tid * 16; i < 2*IMG_W; i += 512*16)
            cp16(smem + W_OFF + i, src + i);
        asm volatile("cp.async.mbarrier.arrive.noinc.shared.b64 [%0];"
                     :: "r"(mbar) : "memory");
    }
    {   // scatter split features (each pipeline its own atom)
        const float* fg = f_ij + (size_t)(ba0 + pid) * NN * NSB;
        __half* ah = reinterpret_cast<__half*>(smem + pid * ATOM_BLK);
        __half* al = reinterpret_cast<__half*>(smem + pid * ATOM_BLK + IMG_A);
        for (int i = lt; i < NN * NSB; i += 256) {
            int r = i / NSB, c = i - (i / NSB) * NSB;
            float v = fg[i];
            __half h = __float2half_rn(v);
            ah[r * PITCH + c] = h;
            al[r * PITCH + c] = __float2half_rn(v - __half2float(h));
        }
    }
    __syncthreads();   // feature images ready

    float acc[8][4];
    uint32_t accL[8][2];

    for (int s = 0; s < 7; s++) {
        // Q: epilogue of previous stage overlaps P's MMAs
        if (pid == 1 && s > 0) {
            epilogue(s - 1, acc, accL, smem, 1, ba0, lw, lane, sBias, sCut, sNbr);
            asm volatile("bar.sync 2, 256;" ::: "memory");   // Q-internal
        }
        #pragma unroll
        for (int nt = 0; nt < 8; nt++) {
            #pragma unroll
            for (int j = 0; j < 4; j++) acc[nt][j] = 0.f;
            accL[nt][0] = 0u; accL[nt][1] = 0u;
        }

        mbar_wait(mbar, (uint32_t)(s & 1));   // W(s) fully arrived

        uint32_t aBase = sb + pid * ATOM_BLK + ((s == 3 || s == 5) ? 2*IMG_A : 0);
        if (s == 0) mm<4>(aBase, sb + W_OFF, acc, accL, lw, lane);
        else        mm<8>(aBase, sb + W_OFF, acc, accL, lw, lane);

        // P: epilogue overlaps Q's MMAs (deferred for s==6: target is W buffer)
        if (pid == 0 && s < 6)
            epilogue(s, acc, accL, smem, 0, ba0, lw, lane, sBias, sCut, sNbr);

        __syncthreads();   // all done reading W(s); P images consistent

        if (s < 6) {       // issue W(s+1); wait happens next window after Q.epi
            const char* src = reinterpret_cast<const char*>(
                d_wsplit + (size_t)(s + 1) * 2 * 128 * PITCH);
            for (int i = tid * 16; i < 2*IMG_W; i += 512*16)
                cp16(smem + W_OFF + i, src + i);
            asm volatile("cp.async.mbarrier.arrive.noinc.shared.b64 [%0];"
                         :: "r"(mbar) : "memory");
        }
    }

    // stage-6 epilogues (both pipelines) -> vikT in W buffer
    epilogue(6, acc, accL, smem, pid, ba0, lw, lane, sBias, sCut, sNbr);
    __syncthreads();

    // ---- Vik[c][d] = sum_n vik[n][c] * cm[n][d] (both atoms) ----
    for (int e = tid; e < 768; e += 512) {
        int atom = e / 384, rem = e - atom * 384;
        int c = rem / 3, d = rem - 3 * (rem / 3);
        const float* vikT = reinterpret_cast<const float*>(smem + W_OFF + atom * IMG_W);
        float s = 0.f;
        #pragma unroll 4
        for (int n = 0; n < 64; n++)
            s = fmaf(vikT[c * VPITCH + n], cmS[(atom*64 + n) * 3 + d], s);
        d_Vik[(size_t)(ba0 + atom) * 384 + rem] = s;
    }

    // ---- vsum from V, atom MLP -> out_vi ----
    if (tid < 256) {
        int atom = tid >> 7, c = tid & 127;
        const __half* vh = reinterpret_cast<const __half*>(smem + atom*ATOM_BLK + 2*IMG_A);
        const __half* vl = reinterpret_cast<const __half*>(smem + atom*ATOM_BLK + 3*IMG_A);
        float s = 0.f;
        #pragma unroll 4
        for (int n = 0; n < 64; n++) {
            float v = __half2float(vh[n * PITCH + c]) + __half2float(vl[n * PITCH + c]);
            s = fmaf(v, sMask[atom*64 + n], s);
        }
        vsumS[tid] = s;
    }
    __syncthreads();
    if (tid < 256) {
        int atom = tid >> 7, c = tid & 127;
        float h = __ldg(ab1 + c);
        #pragma unroll 4
        for (int k = 0; k < 128; k++)
            h = fmaf(vsumS[atom*128 + k], __ldg(aW1 + k * 128 + c), h);
        hidS[tid] = sspf(h);
    }
    __syncthreads();
    if (tid < 256) {
        int atom = tid >> 7, c = tid & 127;
        float o = __ldg(ab2 + c);
        #pragma unroll 4
        for (int k = 0; k < 128; k++)
            o = fmaf(hidS[atom*128 + k], __ldg(aW2 + k * 128 + c), o);
        out_vi[(size_t)(ba0 + atom) * NF + c] = o;
    }
}

// ---------------- kernel: assemble V (direct, float4) ----------------
__global__ void __launch_bounds__(96) k_assemble(
    const float* __restrict__ cos_ij,
    const int* __restrict__ neighbors,
    float* __restrict__ outV) {
    int idx = blockIdx.x;            // (b,a,n) flat
    int tid = threadIdx.x;           // 0..95
    int ba  = idx >> 6;
    int b   = idx >> 14;
    int nb  = __ldg(neighbors + idx);
    int e0  = tid * 4;
    int c0  = e0 / 3;

    float4 vl = *reinterpret_cast<const float4*>(d_Vik + (size_t)ba * 384 + e0);
    float4 vn = *reinterpret_cast<const float4*>(
        d_Vik + ((size_t)(b * AA + nb)) * 384 + e0);
    float cc[3];
    cc[0] = __ldg(cos_ij + (size_t)idx * 3 + 0);
    cc[1] = __ldg(cos_ij + (size_t)idx * 3 + 1);
    cc[2] = __ldg(cos_ij + (size_t)idx * 3 + 2);
    float vij0 = __ldg(d_vij + (size_t)idx * 128 + c0);
    float vij1 = __ldg(d_vij + (size_t)idx * 128 + c0 + 1);

    float vls[4] = {vl.x, vl.y, vl.z, vl.w};
    float vns[4] = {vn.x, vn.y, vn.z, vn.w};
    float4 o;
    float* op = reinterpret_cast<float*>(&o);
    #pragma unroll
    for (int j = 0; j < 4; j++) {
        int e = e0 + j;
        int c = e / 3, d = e - 3 * c;
        float vij = (c == c0) ? vij0 : vij1;
        op[j] = fmaf(vij, cc[d], vls[j] + vns[j]);
    }
    *reinterpret_cast<float4*>(outV + (size_t)idx * 384 + e0) = o;
}

// ---------------- launch ----------------
extern "C" void kernel_launch(void* const* d_in, const int* in_sizes, int n_in,
                              void* d_out, int out_size) {
    const float* xi       = (const float*)d_in[0];
    const float* r_ij     = (const float*)d_in[1];
    const float* cos_ij   = (const float*)d_in[2];
    const float* f_ij     = (const float*)d_in[3];
    const float* nmask    = (const float*)d_in[4];
    const float* fW1      = (const float*)d_in[5];
    const float* fb1      = (const float*)d_in[6];
    const float* fW2      = (const float*)d_in[7];
    const float* fb2      = (const float*)d_in[8];
    const float* in2f_W   = (const float*)d_in[9];
    const float* f2oW     = (const float*)d_in[10];
    const float* f2ob     = (const float*)d_in[11];
    const float* aW1      = (const float*)d_in[12];
    const float* ab1      = (const float*)d_in[13];
    const float* aW2      = (const float*)d_in[14];
    const float* ab2      = (const float*)d_in[15];
    const float* pW1      = (const float*)d_in[16];
    const float* pb1      = (const float*)d_in[17];
    const float* pW2      = (const float*)d_in[18];
    const float* pb2      = (const float*)d_in[19];
    const float* eW1      = (const float*)d_in[20];
    const float* eb1      = (const float*)d_in[21];
    const float* eW2      = (const float*)d_in[22];
    const float* eb2      = (const float*)d_in[23];
    const int*   neighbors= (const int*)d_in[24];

    float* out = (float*)d_out;
    float* out_vi = out;                          // [B,A,NCB]
    float* out_V  = out + (size_t)BB*AA*NCB;      // [B,A,N,NCB,3]

    cudaFuncSetAttribute(k_main, cudaFuncAttributeMaxDynamicSharedMemorySize,
                         (int)SMEM_BYTES);

    k_init<<<7 + BB*AA/2, 256>>>(fW1, fW2, f2oW, pW1, pW2, eW1, eW2, xi, in2f_W);
    k_main<<<BB*AA/2, 512, SMEM_BYTES>>>(
        r_ij, cos_ij, f_ij, nmask,
        fb1, fb2, f2ob, aW1, ab1, aW2, ab2,
        pb1, pb2, eb1, eb2, neighbors, out_vi);
    k_assemble<<<BB*AA*NN, 96>>>(cos_ij, neighbors, out_V);
}

// round 9
// speedup vs baseline: 2.3192x; 1.0852x over previous
#include <cuda_runtime.h>
#include <cuda_fp16.h>
#include <stdint.h>

#define BB  4
#define AA  256
#define NN  64
#define NCB 128
#define NF  128
#define NSB 50

#define PITCH 136
#define IMG_A (64 * PITCH * 2)          // 17408
#define IMG_W (128 * PITCH * 2)         // 34816
#define ATOM_BLK (2 * IMG_A)            // 34816 (Ah, Vh)
#define W_OFF (2 * ATOM_BLK)            // 69632
#define SMEM_BYTES (W_OFF + 2 * IMG_W)  // 139264
#define VPITCH 65

// ---------------- global scratch ----------------
__device__ __align__(16) float d_y[BB*AA*NF];
__device__ __align__(16) float d_vij[(size_t)BB*AA*NN*NCB];
__device__ __align__(16) float d_Vik[BB*AA*NCB*3];
__device__ __align__(16) __half d_wsplit[7 * 2 * 128 * PITCH];

// ---------------- helpers ----------------
__device__ __forceinline__ void cp16(void* sdst, const void* gsrc) {
    unsigned s = (unsigned)__cvta_generic_to_shared(sdst);
    asm volatile("cp.async.cg.shared.global [%0], [%1], 16;" :: "r"(s), "l"(gsrc));
}
__device__ __forceinline__ void ldsm4(uint32_t* r, uint32_t saddr) {
    asm volatile("ldmatrix.sync.aligned.m8n8.x4.shared.b16 {%0,%1,%2,%3}, [%4];"
        : "=r"(r[0]), "=r"(r[1]), "=r"(r[2]), "=r"(r[3]) : "r"(saddr));
}
__device__ __forceinline__ void mma16816(float* c, const uint32_t* a,
                                         uint32_t b0, uint32_t b1) {
    asm volatile("mma.sync.aligned.m16n8k16.row.col.f32.f16.f16.f32 "
        "{%0,%1,%2,%3}, {%4,%5,%6,%7}, {%8,%9}, {%0,%1,%2,%3};"
        : "+f"(c[0]), "+f"(c[1]), "+f"(c[2]), "+f"(c[3])
        : "r"(a[0]), "r"(a[1]), "r"(a[2]), "r"(a[3]), "r"(b0), "r"(b1));
}
// f16-accumulator variant (for the small W-lo correction term)
__device__ __forceinline__ void mma16816h(uint32_t* c, const uint32_t* a,
                                          uint32_t b0, uint32_t b1) {
    asm volatile("mma.sync.aligned.m16n8k16.row.col.f16.f16.f16.f16 "
        "{%0,%1}, {%2,%3,%4,%5}, {%6,%7}, {%0,%1};"
        : "+r"(c[0]), "+r"(c[1])
        : "r"(a[0]), "r"(a[1]), "r"(a[2]), "r"(a[3]), "r"(b0), "r"(b1));
}
__device__ __forceinline__ float sspf(float x) {
    if (x > 15.f) return x - 0.69314718055994531f;
    return __logf(1.f + __expf(x)) - 0.69314718055994531f;
}
__device__ __forceinline__ uint32_t smem_u32(const void* p) {
    return (uint32_t)__cvta_generic_to_shared(p);
}
__device__ __forceinline__ void mbar_wait(uint32_t mb, uint32_t parity) {
    uint32_t done;
    asm volatile("{\n\t.reg .pred p;\n\t"
        "mbarrier.try_wait.parity.acquire.cta.shared::cta.b64 p, [%1], %2;\n\t"
        "selp.b32 %0, 1, 0, p;\n\t}"
        : "=r"(done) : "r"(mb), "r"(parity) : "memory");
    if (!done) {
        asm volatile("{\n\t.reg .pred P1;\n\t"
            "W_%=:\n\t"
            "mbarrier.try_wait.parity.acquire.cta.shared::cta.b64 P1, [%0], %1, 0x989680;\n\t"
            "@P1 bra.uni D_%=;\n\t"
            "bra.uni W_%=;\n\t"
            "D_%=:\n\t}"
            :: "r"(mb), "r"(parity) : "memory");
    }
}

// ---------------- kernel: weight prep + embedding ----------------
__global__ void __launch_bounds__(256) k_init(
    const float* fW1, const float* fW2, const float* f2oW,
    const float* pW1, const float* pW2, const float* eW1, const float* eW2,
    const float* __restrict__ xi, const float* __restrict__ in2f_W) {
    int bid = blockIdx.x;
    if (bid < 7) {
        const float* W; int K, realK;
        switch (bid) {
            case 0: W = fW1;  K = 64;  realK = NSB; break;
            case 1: W = fW2;  K = 128; realK = 128; break;
            case 2: W = f2oW; K = 128; realK = 128; break;
            case 3: W = pW1;  K = 128; realK = 128; break;
            case 4: W = pW2;  K = 128; realK = 128; break;
            case 5: W = eW1;  K = 128; realK = 128; break;
            default: W = eW2; K = 128; realK = 128; break;
        }
        __half* hi = d_wsplit + (size_t)bid * 2 * 128 * PITCH;
        __half* lo = hi + 128 * PITCH;
        for (int i = threadIdx.x; i < 128 * K; i += 256) {
            int n = i / K, k = i - (i / K) * K;
            float v = (k < realK) ? W[k * 128 + n] : 0.f;   // B^T: [n][k]
            __half h = __float2half_rn(v);
            hi[n * PITCH + k] = h;
            lo[n * PITCH + k] = __float2half_rn(v - __half2float(h));
        }
    } else {
        // embedding: 2 rows per block
        int row0 = (bid - 7) * 2;
        int c = threadIdx.x & 127, g = threadIdx.x >> 7;
        __shared__ float sx[2][128];
        sx[g][c] = xi[(size_t)(row0 + g) * 128 + c];
        __syncthreads();
        float a0 = 0.f;
        #pragma unroll 8
        for (int k = 0; k < 128; k++)
            a0 = fmaf(sx[g][k], __ldg(in2f_W + k * 128 + c), a0);
        d_y[(size_t)(row0 + g) * 128 + c] = a0;
    }
}

// 2-product GEMM: Ah*Wh -> f32 acc, Ah*Wl -> f16 acc
template<int KSTEPS>
__device__ __forceinline__ void mm(uint32_t aBase, uint32_t wBase,
                                   float (&acc)[8][4], uint32_t (&accL)[8][2],
                                   int lw, int lane) {
    const int warp_m = lw & 3, warp_h = lw >> 2;
    const int rsel = lane & 15, hsel = lane >> 4;
    uint32_t aAddr = aBase + (uint32_t)(((warp_m*16 + rsel) * PITCH + hsel*8) * 2);
    uint32_t wAddr = wBase + (uint32_t)(((warp_h*64 + rsel) * PITCH + hsel*8) * 2);
    const uint32_t STEP16 = 16 * PITCH * 2;
    #pragma unroll 1
    for (int kk = 0; kk < KSTEPS; kk++) {
        uint32_t Ah[4], Wh[4][4], Wl[4][4];
        uint32_t ak = aAddr + kk * 32;
        uint32_t wk = wAddr + kk * 32;
        ldsm4(Ah, ak);
        #pragma unroll
        for (int q = 0; q < 4; q++) {
            ldsm4(Wh[q], wk + q * STEP16);
            ldsm4(Wl[q], wk + q * STEP16 + IMG_W);
        }
        #pragma unroll
        for (int q = 0; q < 4; q++)
            #pragma unroll
            for (int j = 0; j < 2; j++) {
                int nt = q * 2 + j;
                mma16816(acc[nt], Ah, Wh[q][j], Wh[q][j+2]);       // Ah*Wh -> f32
                mma16816h(accL[nt], Ah, Wl[q][j], Wl[q][j+2]);     // Ah*Wl -> f16
            }
    }
}

// stage epilogue for one pipeline
__device__ __forceinline__ void epilogue(
    int s, float (&acc)[8][4], uint32_t (&accL)[8][2], char* smem, int pid, int ba0,
    int lw, int lane, const float (*sBias)[128],
    const float* sCut, const int* sNbr)
{
    const int warp_m = lw & 3, warp_h = lw >> 2;
    const int er = lane >> 2, ec2 = (lane & 3) * 2;
    char* atomBase = smem + pid * ATOM_BLK;
    char* dstH = atomBase + ((s == 2) ? IMG_A : 0);
    float* vikT = reinterpret_cast<float*>(smem + W_OFF + pid * IMG_W);
    const int baG = ba0 + pid;
    const int bA = baG >> 8;
    #pragma unroll
    for (int nt = 0; nt < 8; nt++) {
        int col = warp_h*64 + nt*8 + ec2;
        float b0 = sBias[s][col], b1 = sBias[s][col + 1];
        #pragma unroll
        for (int h = 0; h < 2; h++) {
            int row = warp_m*16 + er + h*8;        // 0..63
            int grow = pid*64 + row;
            __half2 lo2 = *reinterpret_cast<__half2*>(&accL[nt][h]);
            float x0 = acc[nt][h*2+0] + __half2float(lo2.x) + b0;
            float x1 = acc[nt][h*2+1] + __half2float(lo2.y) + b1;
            if (s == 1) {
                float cu = sCut[grow];
                const float2 y = *reinterpret_cast<const float2*>(
                    d_y + ((size_t)((bA << 8) + sNbr[grow]) << 7) + col);
                x0 = x0 * cu * y.x;
                x1 = x1 * cu * y.y;
            } else if (s == 4) {
                *reinterpret_cast<float2*>(
                    d_vij + ((size_t)baG * 64 + row) * 128 + col) =
                    make_float2(x0, x1);
                continue;
            } else if (s == 6) {
                vikT[col * VPITCH + row]       = x0;
                vikT[(col + 1) * VPITCH + row] = x1;
                continue;
            } else {
                x0 = sspf(x0); x1 = sspf(x1);
            }
            __half2 hp = __floats2half2_rn(x0, x1);
            uint32_t off = (uint32_t)(row * PITCH + col) * 2;
            *reinterpret_cast<uint32_t*>(dstH + off) = *reinterpret_cast<uint32_t*>(&hp);
        }
    }
}

// ---------------- kernel: fused interaction, 2 staggered pipelines ---------
__global__ void __launch_bounds__(512, 1) k_main(
    const float* __restrict__ r_ij, const float* __restrict__ cos_ij,
    const float* __restrict__ f_ij, const float* __restrict__ nmask,
    const float* __restrict__ fb1, const float* __restrict__ fb2,
    const float* __restrict__ f2ob,
    const float* __restrict__ aW1, const float* __restrict__ ab1,
    const float* __restrict__ aW2, const float* __restrict__ ab2,
    const float* __restrict__ pb1, const float* __restrict__ pb2,
    const float* __restrict__ eb1, const float* __restrict__ eb2,
    const int* __restrict__ neighbors, float* __restrict__ out_vi)
{
    extern __shared__ char smem[];
    const uint32_t sb = smem_u32(smem);
    const int tid = threadIdx.x;
    const int pid = tid >> 8;            // pipeline/atom: 0 or 1
    const int lt  = tid & 255, lw = lt >> 5, lane = tid & 31;
    const int ba0 = blockIdx.x * 2;

    __shared__ float sCut[128], sMask[128], cmS[384], vsumS[256], hidS[256];
    __shared__ float sBias[7][128];
    __shared__ int   sNbr[128];
    __shared__ __align__(8) uint64_t mbarW;
    const uint32_t mbar = smem_u32(&mbarW);

    if (tid == 0)
        asm volatile("mbarrier.init.shared.b64 [%0], %1;"
                     :: "r"(mbar), "r"(512u) : "memory");

    {   // biases to smem
        const float* bp[7] = {fb1, fb2, f2ob, pb1, pb2, eb1, eb2};
        for (int i = tid; i < 7*128; i += 512)
            sBias[i >> 7][i & 127] = __ldg(bp[i >> 7] + (i & 127));
    }
    if (tid < 128) {
        int g = ba0 * NN + tid;
        float r = r_ij[g];
        sCut[tid]  = (r < 5.f) ? 0.5f * (__cosf(r * 0.62831853071795864f) + 1.f) : 0.f;
        float m = nmask[g];
        sMask[tid] = m;
        sNbr[tid]  = neighbors[g];
        cmS[tid*3+0] = cos_ij[(size_t)g*3+0] * m;
        cmS[tid*3+1] = cos_ij[(size_t)g*3+1] * m;
        cmS[tid*3+2] = cos_ij[(size_t)g*3+2] * m;
    }
    {   // zero both atoms' A images
        uint64_t* z = reinterpret_cast<uint64_t*>(smem);
        for (int i = tid; i < (2*ATOM_BLK)/8; i += 512) z[i] = 0ull;
    }
    __syncthreads();   // mbar init + zero visible

    {   // issue W(0) + mbarrier arrive-on-completion
        const char* src = reinterpret_cast<const char*>(d_wsplit);
        for (int i = tid * 16; i < 2*IMG_W; i += 512*16)
            cp16(smem + W_OFF + i, src + i);
        asm volatile("cp.async.mbarrier.arrive.noinc.shared.b64 [%0];"
                     :: "r"(mbar) : "memory");
    }
    {   // scatter features (fp16 only)
        const float* fg = f_ij + (size_t)(ba0 + pid) * NN * NSB;
        __half* ah = reinterpret_cast<__half*>(smem + pid * ATOM_BLK);
        for (int i = lt; i < NN * NSB; i += 256) {
            int r = i / NSB, c = i - (i / NSB) * NSB;
            ah[r * PITCH + c] = __float2half_rn(fg[i]);
        }
    }
    __syncthreads();   // feature images ready

    float acc[8][4];
    uint32_t accL[8][2];

    for (int s = 0; s < 7; s++) {
        // Q: epilogue of previous stage overlaps P's MMAs
        if (pid == 1 && s > 0) {
            epilogue(s - 1, acc, accL, smem, 1, ba0, lw, lane, sBias, sCut, sNbr);
            asm volatile("bar.sync 2, 256;" ::: "memory");   // Q-internal
        }
        #pragma unroll
        for (int nt = 0; nt < 8; nt++) {
            #pragma unroll
            for (int j = 0; j < 4; j++) acc[nt][j] = 0.f;
            accL[nt][0] = 0u; accL[nt][1] = 0u;
        }

        mbar_wait(mbar, (uint32_t)(s & 1));   // W(s) fully arrived

        uint32_t aBase = sb + pid * ATOM_BLK + ((s == 3 || s == 5) ? IMG_A : 0);
        if (s == 0) mm<4>(aBase, sb + W_OFF, acc, accL, lw, lane);
        else        mm<8>(aBase, sb + W_OFF, acc, accL, lw, lane);

        // P: epilogue overlaps Q's MMAs (deferred for s==6: target is W buffer)
        if (pid == 0 && s < 6)
            epilogue(s, acc, accL, smem, 0, ba0, lw, lane, sBias, sCut, sNbr);

        __syncthreads();   // all done reading W(s); P images consistent

        if (s < 6) {       // issue W(s+1); wait happens next window after Q.epi
            const char* src = reinterpret_cast<const char*>(
                d_wsplit + (size_t)(s + 1) * 2 * 128 * PITCH);
            for (int i = tid * 16; i < 2*IMG_W; i += 512*16)
                cp16(smem + W_OFF + i, src + i);
            asm volatile("cp.async.mbarrier.arrive.noinc.shared.b64 [%0];"
                         :: "r"(mbar) : "memory");
        }
    }

    // stage-6 epilogues (both pipelines) -> vikT in W buffer
    epilogue(6, acc, accL, smem, pid, ba0, lw, lane, sBias, sCut, sNbr);
    __syncthreads();

    // ---- Vik[c][d] = sum_n vik[n][c] * cm[n][d] (both atoms) ----
    for (int e = tid; e < 768; e += 512) {
        int atom = e / 384, rem = e - atom * 384;
        int c = rem / 3, d = rem - 3 * (rem / 3);
        const float* vikT = reinterpret_cast<const float*>(smem + W_OFF + atom * IMG_W);
        float s = 0.f;
        #pragma unroll 4
        for (int n = 0; n < 64; n++)
            s = fmaf(vikT[c * VPITCH + n], cmS[(atom*64 + n) * 3 + d], s);
        d_Vik[(size_t)(ba0 + atom) * 384 + rem] = s;
    }

    // ---- vsum from V (fp16 image), atom MLP -> out_vi ----
    if (tid < 256) {
        int atom = tid >> 7, c = tid & 127;
        const __half* vh = reinterpret_cast<const __half*>(smem + atom*ATOM_BLK + IMG_A);
        float s = 0.f;
        #pragma unroll 4
        for (int n = 0; n < 64; n++)
            s = fmaf(__half2float(vh[n * PITCH + c]), sMask[atom*64 + n], s);
        vsumS[tid] = s;
    }
    __syncthreads();
    if (tid < 256) {
        int atom = tid >> 7, c = tid & 127;
        float h = __ldg(ab1 + c);
        #pragma unroll 4
        for (int k = 0; k < 128; k++)
            h = fmaf(vsumS[atom*128 + k], __ldg(aW1 + k * 128 + c), h);
        hidS[tid] = sspf(h);
    }
    __syncthreads();
    if (tid < 256) {
        int atom = tid >> 7, c = tid & 127;
        float o = __ldg(ab2 + c);
        #pragma unroll 4
        for (int k = 0; k < 128; k++)
            o = fmaf(hidS[atom*128 + k], __ldg(aW2 + k * 128 + c), o);
        out_vi[(size_t)(ba0 + atom) * NF + c] = o;
    }
}

// ---------------- kernel: assemble V (direct, float4) ----------------
__global__ void __launch_bounds__(96) k_assemble(
    const float* __restrict__ cos_ij,
    const int* __restrict__ neighbors,
    float* __restrict__ outV) {
    int idx = blockIdx.x;            // (b,a,n) flat
    int tid = threadIdx.x;           // 0..95
    int ba  = idx >> 6;
    int b   = idx >> 14;
    int nb  = __ldg(neighbors + idx);
    int e0  = tid * 4;
    int c0  = e0 / 3;

    float4 vl = *reinterpret_cast<const float4*>(d_Vik + (size_t)ba * 384 + e0);
    float4 vn = *reinterpret_cast<const float4*>(
        d_Vik + ((size_t)(b * AA + nb)) * 384 + e0);
    float cc[3];
    cc[0] = __ldg(cos_ij + (size_t)idx * 3 + 0);
    cc[1] = __ldg(cos_ij + (size_t)idx * 3 + 1);
    cc[2] = __ldg(cos_ij + (size_t)idx * 3 + 2);
    float vij0 = __ldg(d_vij + (size_t)idx * 128 + c0);
    float vij1 = __ldg(d_vij + (size_t)idx * 128 + c0 + 1);

    float vls[4] = {vl.x, vl.y, vl.z, vl.w};
    float vns[4] = {vn.x, vn.y, vn.z, vn.w};
    float4 o;
    float* op = reinterpret_cast<float*>(&o);
    #pragma unroll
    for (int j = 0; j < 4; j++) {
        int e = e0 + j;
        int c = e / 3, d = e - 3 * c;
        float vij = (c == c0) ? vij0 : vij1;
        op[j] = fmaf(vij, cc[d], vls[j] + vns[j]);
    }
    *reinterpret_cast<float4*>(outV + (size_t)idx * 384 + e0) = o;
}

// ---------------- launch ----------------
extern "C" void kernel_launch(void* const* d_in, const int* in_sizes, int n_in,
                              void* d_out, int out_size) {
    const float* xi       = (const float*)d_in[0];
    const float* r_ij     = (const float*)d_in[1];
    const float* cos_ij   = (const float*)d_in[2];
    const float* f_ij     = (const float*)d_in[3];
    const float* nmask    = (const float*)d_in[4];
    const float* fW1      = (const float*)d_in[5];
    const float* fb1      = (const float*)d_in[6];
    const float* fW2      = (const float*)d_in[7];
    const float* fb2      = (const float*)d_in[8];
    const float* in2f_W   = (const float*)d_in[9];
    const float* f2oW     = (const float*)d_in[10];
    const float* f2ob     = (const float*)d_in[11];
    const float* aW1      = (const float*)d_in[12];
    const float* ab1      = (const float*)d_in[13];
    const float* aW2      = (const float*)d_in[14];
    const float* ab2      = (const float*)d_in[15];
    const float* pW1      = (const float*)d_in[16];
    const float* pb1      = (const float*)d_in[17];
    const float* pW2      = (const float*)d_in[18];
    const float* pb2      = (const float*)d_in[19];
    const float* eW1      = (const float*)d_in[20];
    const float* eb1      = (const float*)d_in[21];
    const float* eW2      = (const float*)d_in[22];
    const float* eb2      = (const float*)d_in[23];
    const int*   neighbors= (const int*)d_in[24];

    float* out = (float*)d_out;
    float* out_vi = out;                          // [B,A,NCB]
    float* out_V  = out + (size_t)BB*AA*NCB;      // [B,A,N,NCB,3]

    cudaFuncSetAttribute(k_main, cudaFuncAttributeMaxDynamicSharedMemorySize,
                         (int)SMEM_BYTES);

    k_init<<<7 + BB*AA/2, 256>>>(fW1, fW2, f2oW, pW1, pW2, eW1, eW2, xi, in2f_W);
    k_main<<<BB*AA/2, 512, SMEM_BYTES>>>(
        r_ij, cos_ij, f_ij, nmask,
        fb1, fb2, f2ob, aW1, ab1, aW2, ab2,
        pb1, pb2, eb1, eb2, neighbors, out_vi);
    k_assemble<<<BB*AA*NN, 96>>>(cos_ij, neighbors, out_V);
}

// round 10
// speedup vs baseline: 2.5033x; 1.0794x over previous
#include <cuda_runtime.h>
#include <cuda_fp16.h>
#include <stdint.h>

#define BB  4
#define AA  256
#define NN  64
#define NCB 128
#define NF  128
#define NSB 50

#define PITCH 136
#define IMG_A (64 * PITCH * 2)          // 17408
#define IMG_W (128 * PITCH * 2)         // 34816
#define ATOM_BLK (2 * IMG_A)            // 34816 (Ah, Vh per atom)
#define WBUF (2 * IMG_W)                // 69632 (hi + lo)
#define W0_OFF (2 * ATOM_BLK)           // 69632
#define W1_OFF (W0_OFF + WBUF)          // 139264
#define SMEM_BYTES (W1_OFF + WBUF)      // 208896
#define VPITCH 65

// ---------------- global scratch ----------------
__device__ __align__(16) float d_y[BB*AA*NF];
__device__ __align__(16) float d_vij[(size_t)BB*AA*NN*NCB];
__device__ __align__(16) float d_Vik[BB*AA*NCB*3];
__device__ __align__(16) __half d_wsplit[7 * 2 * 128 * PITCH];

// ---------------- helpers ----------------
__device__ __forceinline__ void cp16(void* sdst, const void* gsrc) {
    unsigned s = (unsigned)__cvta_generic_to_shared(sdst);
    asm volatile("cp.async.cg.shared.global [%0], [%1], 16;" :: "r"(s), "l"(gsrc));
}
__device__ __forceinline__ void ldsm4(uint32_t* r, uint32_t saddr) {
    asm volatile("ldmatrix.sync.aligned.m8n8.x4.shared.b16 {%0,%1,%2,%3}, [%4];"
        : "=r"(r[0]), "=r"(r[1]), "=r"(r[2]), "=r"(r[3]) : "r"(saddr));
}
__device__ __forceinline__ void mma16816(float* c, const uint32_t* a,
                                         uint32_t b0, uint32_t b1) {
    asm volatile("mma.sync.aligned.m16n8k16.row.col.f32.f16.f16.f32 "
        "{%0,%1,%2,%3}, {%4,%5,%6,%7}, {%8,%9}, {%0,%1,%2,%3};"
        : "+f"(c[0]), "+f"(c[1]), "+f"(c[2]), "+f"(c[3])
        : "r"(a[0]), "r"(a[1]), "r"(a[2]), "r"(a[3]), "r"(b0), "r"(b1));
}
__device__ __forceinline__ void mma16816h(uint32_t* c, const uint32_t* a,
                                          uint32_t b0, uint32_t b1) {
    asm volatile("mma.sync.aligned.m16n8k16.row.col.f16.f16.f16.f16 "
        "{%0,%1}, {%2,%3,%4,%5}, {%6,%7}, {%0,%1};"
        : "+r"(c[0]), "+r"(c[1])
        : "r"(a[0]), "r"(a[1]), "r"(a[2]), "r"(a[3]), "r"(b0), "r"(b1));
}
__device__ __forceinline__ float sspf(float x) {
    if (x > 15.f) return x - 0.69314718055994531f;
    return __logf(1.f + __expf(x)) - 0.69314718055994531f;
}
__device__ __forceinline__ uint32_t smem_u32(const void* p) {
    return (uint32_t)__cvta_generic_to_shared(p);
}
__device__ __forceinline__ void mbar_wait(uint32_t mb, uint32_t parity) {
    uint32_t done;
    asm volatile("{\n\t.reg .pred p;\n\t"
        "mbarrier.try_wait.parity.acquire.cta.shared::cta.b64 p, [%1], %2;\n\t"
        "selp.b32 %0, 1, 0, p;\n\t}"
        : "=r"(done) : "r"(mb), "r"(parity) : "memory");
    if (!done) {
        asm volatile("{\n\t.reg .pred P1;\n\t"
            "W_%=:\n\t"
            "mbarrier.try_wait.parity.acquire.cta.shared::cta.b64 P1, [%0], %1, 0x989680;\n\t"
            "@P1 bra.uni D_%=;\n\t"
            "bra.uni W_%=;\n\t"
            "D_%=:\n\t}"
            :: "r"(mb), "r"(parity) : "memory");
    }
}

// ---------------- kernel: weight prep + embedding ----------------
__global__ void __launch_bounds__(256) k_init(
    const float* fW1, const float* fW2, const float* f2oW,
    const float* pW1, const float* pW2, const float* eW1, const float* eW2,
    const float* __restrict__ xi, const float* __restrict__ in2f_W) {
    int bid = blockIdx.x;
    if (bid < 7) {
        const float* W; int K, realK;
        switch (bid) {
            case 0: W = fW1;  K = 64;  realK = NSB; break;
            case 1: W = fW2;  K = 128; realK = 128; break;
            case 2: W = f2oW; K = 128; realK = 128; break;
            case 3: W = pW1;  K = 128; realK = 128; break;
            case 4: W = pW2;  K = 128; realK = 128; break;
            case 5: W = eW1;  K = 128; realK = 128; break;
            default: W = eW2; K = 128; realK = 128; break;
        }
        __half* hi = d_wsplit + (size_t)bid * 2 * 128 * PITCH;
        __half* lo = hi + 128 * PITCH;
        for (int i = threadIdx.x; i < 128 * K; i += 256) {
            int n = i / K, k = i - (i / K) * K;
            float v = (k < realK) ? W[k * 128 + n] : 0.f;   // B^T: [n][k]
            __half h = __float2half_rn(v);
            hi[n * PITCH + k] = h;
            lo[n * PITCH + k] = __float2half_rn(v - __half2float(h));
        }
    } else {
        int row0 = (bid - 7) * 2;
        int c = threadIdx.x & 127, g = threadIdx.x >> 7;
        __shared__ float sx[2][128];
        sx[g][c] = xi[(size_t)(row0 + g) * 128 + c];
        __syncthreads();
        float a0 = 0.f;
        #pragma unroll 8
        for (int k = 0; k < 128; k++)
            a0 = fmaf(sx[g][k], __ldg(in2f_W + k * 128 + c), a0);
        d_y[(size_t)(row0 + g) * 128 + c] = a0;
    }
}

// 2-product GEMM, m32n32 warp tile, software-pipelined k-loop.
template<int KSTEPS>
__device__ __forceinline__ void mm(uint32_t aBase, uint32_t wBase,
                                   float (&acc)[8][4], uint32_t (&accL)[8][2],
                                   int lw, int lane) {
    const int warp_m = (lw >> 2) & 1, warp_n = lw & 3;
    const int rsel = lane & 15, hsel = lane >> 4;
    uint32_t aAddr = aBase + (uint32_t)(((warp_m*32 + rsel) * PITCH + hsel*8) * 2);
    uint32_t wAddr = wBase + (uint32_t)(((warp_n*32 + rsel) * PITCH + hsel*8) * 2);
    const uint32_t STEP16 = 16 * PITCH * 2;

    uint32_t A[2][2][4], Wh[2][2][4], Wl[2][2][4];   // [buf][frag][reg]
    // prologue: kstep 0
    ldsm4(A[0][0],  aAddr);
    ldsm4(A[0][1],  aAddr + STEP16);
    ldsm4(Wh[0][0], wAddr);
    ldsm4(Wh[0][1], wAddr + STEP16);
    ldsm4(Wl[0][0], wAddr + IMG_W);
    ldsm4(Wl[0][1], wAddr + IMG_W + STEP16);

    #pragma unroll
    for (int kk = 0; kk < KSTEPS; kk++) {
        const int cur = kk & 1, nxt = cur ^ 1;
        if (kk + 1 < KSTEPS) {
            uint32_t ak = aAddr + (kk + 1) * 32;
            uint32_t wk = wAddr + (kk + 1) * 32;
            ldsm4(A[nxt][0],  ak);
            ldsm4(A[nxt][1],  ak + STEP16);
            ldsm4(Wh[nxt][0], wk);
            ldsm4(Wh[nxt][1], wk + STEP16);
            ldsm4(Wl[nxt][0], wk + IMG_W);
            ldsm4(Wl[nxt][1], wk + IMG_W + STEP16);
        }
        #pragma unroll
        for (int mt = 0; mt < 2; mt++)
            #pragma unroll
            for (int q = 0; q < 2; q++)
                #pragma unroll
                for (int j = 0; j < 2; j++) {
                    int t = mt*4 + q*2 + j;
                    mma16816(acc[t],  A[cur][mt], Wh[cur][q][j], Wh[cur][q][j+2]);
                    mma16816h(accL[t], A[cur][mt], Wl[cur][q][j], Wl[cur][q][j+2]);
                }
    }
}

// stage epilogue for one pipeline (m32n32 tile mapping)
__device__ __forceinline__ void epilogue(
    int s, float (&acc)[8][4], uint32_t (&accL)[8][2], char* smem, int pid, int ba0,
    int lw, int lane, const float (*sBias)[128],
    const float* sCut, const int* sNbr)
{
    const int warp_m = (lw >> 2) & 1, warp_n = lw & 3;
    const int er = lane >> 2, ec2 = (lane & 3) * 2;
    char* atomBase = smem + pid * ATOM_BLK;
    char* dstH = atomBase + ((s == 2) ? IMG_A : 0);
    float* vikT = reinterpret_cast<float*>(smem + W1_OFF + pid * IMG_W);
    const int baG = ba0 + pid;
    const int bA = baG >> 8;
    #pragma unroll
    for (int mt = 0; mt < 2; mt++) {
        #pragma unroll
        for (int nt = 0; nt < 4; nt++) {
            int t = mt*4 + nt;
            int col = warp_n*32 + nt*8 + ec2;
            float b0 = sBias[s][col], b1 = sBias[s][col + 1];
            #pragma unroll
            for (int h = 0; h < 2; h++) {
                int row = warp_m*32 + mt*16 + er + h*8;   // 0..63
                int grow = pid*64 + row;
                __half2 lo2 = *reinterpret_cast<__half2*>(&accL[t][h]);
                float x0 = acc[t][h*2+0] + __half2float(lo2.x) + b0;
                float x1 = acc[t][h*2+1] + __half2float(lo2.y) + b1;
                if (s == 1) {
                    float cu = sCut[grow];
                    const float2 y = *reinterpret_cast<const float2*>(
                        d_y + ((size_t)((bA << 8) + sNbr[grow]) << 7) + col);
                    x0 = x0 * cu * y.x;
                    x1 = x1 * cu * y.y;
                } else if (s == 4) {
                    *reinterpret_cast<float2*>(
                        d_vij + ((size_t)baG * 64 + row) * 128 + col) =
                        make_float2(x0, x1);
                    continue;
                } else if (s == 6) {
                    vikT[col * VPITCH + row]       = x0;
                    vikT[(col + 1) * VPITCH + row] = x1;
                    continue;
                } else {
                    x0 = sspf(x0); x1 = sspf(x1);
                }
                __half2 hp = __floats2half2_rn(x0, x1);
                uint32_t off = (uint32_t)(row * PITCH + col) * 2;
                *reinterpret_cast<uint32_t*>(dstH + off) = *reinterpret_cast<uint32_t*>(&hp);
            }
        }
    }
}

// ---------------- kernel: fused interaction, double-buffered W -------------
__global__ void __launch_bounds__(512, 1) k_main(
    const float* __restrict__ r_ij, const float* __restrict__ cos_ij,
    const float* __restrict__ f_ij, const float* __restrict__ nmask,
    const float* __restrict__ fb1, const float* __restrict__ fb2,
    const float* __restrict__ f2ob,
    const float* __restrict__ aW1, const float* __restrict__ ab1,
    const float* __restrict__ aW2, const float* __restrict__ ab2,
    const float* __restrict__ pb1, const float* __restrict__ pb2,
    const float* __restrict__ eb1, const float* __restrict__ eb2,
    const int* __restrict__ neighbors, float* __restrict__ out_vi)
{
    extern __shared__ char smem[];
    const uint32_t sb = smem_u32(smem);
    const int tid = threadIdx.x;
    const int pid = tid >> 8;            // pipeline/atom: 0 or 1
    const int lt  = tid & 255, lw = lt >> 5, lane = tid & 31;
    const int ba0 = blockIdx.x * 2;

    __shared__ float sCut[128], sMask[128], cmS[384], vsumS[256], hidS[256];
    __shared__ float sBias[7][128];
    __shared__ int   sNbr[128];
    __shared__ __align__(8) uint64_t mbarW[2];
    const uint32_t mbar0 = smem_u32(&mbarW[0]);
    const uint32_t mbar1 = smem_u32(&mbarW[1]);

    if (tid == 0) {
        asm volatile("mbarrier.init.shared.b64 [%0], %1;" :: "r"(mbar0), "r"(512u) : "memory");
        asm volatile("mbarrier.init.shared.b64 [%0], %1;" :: "r"(mbar1), "r"(512u) : "memory");
    }

    {   // biases to smem
        const float* bp[7] = {fb1, fb2, f2ob, pb1, pb2, eb1, eb2};
        for (int i = tid; i < 7*128; i += 512)
            sBias[i >> 7][i & 127] = __ldg(bp[i >> 7] + (i & 127));
    }
    if (tid < 128) {
        int g = ba0 * NN + tid;
        float r = r_ij[g];
        sCut[tid]  = (r < 5.f) ? 0.5f * (__cosf(r * 0.62831853071795864f) + 1.f) : 0.f;
        float m = nmask[g];
        sMask[tid] = m;
        sNbr[tid]  = neighbors[g];
        cmS[tid*3+0] = cos_ij[(size_t)g*3+0] * m;
        cmS[tid*3+1] = cos_ij[(size_t)g*3+1] * m;
        cmS[tid*3+2] = cos_ij[(size_t)g*3+2] * m;
    }
    {   // zero both atoms' images
        uint64_t* z = reinterpret_cast<uint64_t*>(smem);
        for (int i = tid; i < (2*ATOM_BLK)/8; i += 512) z[i] = 0ull;
    }
    __syncthreads();   // mbar init + zero visible

    {   // issue W(0) -> buf0
        const char* src = reinterpret_cast<const char*>(d_wsplit);
        for (int i = tid * 16; i < WBUF; i += 512*16)
            cp16(smem + W0_OFF + i, src + i);
        asm volatile("cp.async.mbarrier.arrive.noinc.shared.b64 [%0];"
                     :: "r"(mbar0) : "memory");
    }
    {   // scatter features (fp16)
        const float* fg = f_ij + (size_t)(ba0 + pid) * NN * NSB;
        __half* ah = reinterpret_cast<__half*>(smem + pid * ATOM_BLK);
        for (int i = lt; i < NN * NSB; i += 256) {
            int r = i / NSB, c = i - (i / NSB) * NSB;
            ah[r * PITCH + c] = __float2half_rn(fg[i]);
        }
    }
    __syncthreads();   // feature images ready

    float acc[8][4];
    uint32_t accL[8][2];

    for (int s = 0; s < 7; s++) {
        // issue W(s+1) into the other buffer — a full stage of lead
        if (s < 6) {
            const char* src = reinterpret_cast<const char*>(
                d_wsplit + (size_t)(s + 1) * 2 * 128 * PITCH);
            uint32_t woff = ((s + 1) & 1) ? W1_OFF : W0_OFF;
            for (int i = tid * 16; i < WBUF; i += 512*16)
                cp16(smem + woff + i, src + i);
            asm volatile("cp.async.mbarrier.arrive.noinc.shared.b64 [%0];"
                         :: "r"(((s + 1) & 1) ? mbar1 : mbar0) : "memory");
        }

        // Q: epilogue of previous stage overlaps P's MMAs
        if (pid == 1 && s > 0) {
            epilogue(s - 1, acc, accL, smem, 1, ba0, lw, lane, sBias, sCut, sNbr);
            asm volatile("bar.sync 2, 256;" ::: "memory");   // Q-internal
        }
        #pragma unroll
        for (int t = 0; t < 8; t++) {
            #pragma unroll
            for (int j = 0; j < 4; j++) acc[t][j] = 0.f;
            accL[t][0] = 0u; accL[t][1] = 0u;
        }

        mbar_wait((s & 1) ? mbar1 : mbar0, (uint32_t)((s >> 1) & 1));

        uint32_t aBase = sb + pid * ATOM_BLK + ((s == 3 || s == 5) ? IMG_A : 0);
        uint32_t wBase = sb + ((s & 1) ? W1_OFF : W0_OFF);
        if (s == 0) mm<4>(aBase, wBase, acc, accL, lw, lane);
        else        mm<8>(aBase, wBase, acc, accL, lw, lane);

        // P: epilogue overlaps Q's MMAs
        if (pid == 0 && s < 6)
            epilogue(s, acc, accL, smem, 0, ba0, lw, lane, sBias, sCut, sNbr);

        __syncthreads();
    }

    // stage-6 epilogues (both pipelines) -> vikT in W1 buffer (stage 6 read buf0)
    epilogue(6, acc, accL, smem, pid, ba0, lw, lane, sBias, sCut, sNbr);
    __syncthreads();

    // ---- Vik[c][d] = sum_n vik[n][c] * cm[n][d] (both atoms) ----
    for (int e = tid; e < 768; e += 512) {
        int atom = e / 384, rem = e - atom * 384;
        int c = rem / 3, d = rem - 3 * (rem / 3);
        const float* vikT = reinterpret_cast<const float*>(smem + W1_OFF + atom * IMG_W);
        float s = 0.f;
        #pragma unroll 4
        for (int n = 0; n < 64; n++)
            s = fmaf(vikT[c * VPITCH + n], cmS[(atom*64 + n) * 3 + d], s);
        d_Vik[(size_t)(ba0 + atom) * 384 + rem] = s;
    }

    // ---- vsum from V (fp16 image), atom MLP -> out_vi ----
    if (tid < 256) {
        int atom = tid >> 7, c = tid & 127;
        const __half* vh = reinterpret_cast<const __half*>(smem + atom*ATOM_BLK + IMG_A);
        float s = 0.f;
        #pragma unroll 4
        for (int n = 0; n < 64; n++)
            s = fmaf(__half2float(vh[n * PITCH + c]), sMask[atom*64 + n], s);
        vsumS[tid] = s;
    }
    __syncthreads();
    if (tid < 256) {
        int atom = tid >> 7, c = tid & 127;
        float h = __ldg(ab1 + c);
        #pragma unroll 4
        for (int k = 0; k < 128; k++)
            h = fmaf(vsumS[atom*128 + k], __ldg(aW1 + k * 128 + c), h);
        hidS[tid] = sspf(h);
    }
    __syncthreads();
    if (tid < 256) {
        int atom = tid >> 7, c = tid & 127;
        float o = __ldg(ab2 + c);
        #pragma unroll 4
        for (int k = 0; k < 128; k++)
            o = fmaf(hidS[atom*128 + k], __ldg(aW2 + k * 128 + c), o);
        out_vi[(size_t)(ba0 + atom) * NF + c] = o;
    }
}

// ---------------- kernel: assemble V (direct, float4) ----------------
__global__ void __launch_bounds__(96) k_assemble(
    const float* __restrict__ cos_ij,
    const int* __restrict__ neighbors,
    float* __restrict__ outV) {
    int idx = blockIdx.x;            // (b,a,n) flat
    int tid = threadIdx.x;           // 0..95
    int ba  = idx >> 6;
    int b   = idx >> 14;
    int nb  = __ldg(neighbors + idx);
    int e0  = tid * 4;
    int c0  = e0 / 3;

    float4 vl = *reinterpret_cast<const float4*>(d_Vik + (size_t)ba * 384 + e0);
    float4 vn = *reinterpret_cast<const float4*>(
        d_Vik + ((size_t)(b * AA + nb)) * 384 + e0);
    float cc[3];
    cc[0] = __ldg(cos_ij + (size_t)idx * 3 + 0);
    cc[1] = __ldg(cos_ij + (size_t)idx * 3 + 1);
    cc[2] = __ldg(cos_ij + (size_t)idx * 3 + 2);
    float vij0 = __ldg(d_vij + (size_t)idx * 128 + c0);
    float vij1 = __ldg(d_vij + (size_t)idx * 128 + c0 + 1);

    float vls[4] = {vl.x, vl.y, vl.z, vl.w};
    float vns[4] = {vn.x, vn.y, vn.z, vn.w};
    float4 o;
    float* op = reinterpret_cast<float*>(&o);
    #pragma unroll
    for (int j = 0; j < 4; j++) {
        int e = e0 + j;
        int c = e / 3, d = e - 3 * c;
        float vij = (c == c0) ? vij0 : vij1;
        op[j] = fmaf(vij, cc[d], vls[j] + vns[j]);
    }
    *reinterpret_cast<float4*>(outV + (size_t)idx * 384 + e0) = o;
}

// ---------------- launch ----------------
extern "C" void kernel_launch(void* const* d_in, const int* in_sizes, int n_in,
                              void* d_out, int out_size) {
    const float* xi       = (const float*)d_in[0];
    const float* r_ij     = (const float*)d_in[1];
    const float* cos_ij   = (const float*)d_in[2];
    const float* f_ij     = (const float*)d_in[3];
    const float* nmask    = (const float*)d_in[4];
    const float* fW1      = (const float*)d_in[5];
    const float* fb1      = (const float*)d_in[6];
    const float* fW2      = (const float*)d_in[7];
    const float* fb2      = (const float*)d_in[8];
    const float* in2f_W   = (const float*)d_in[9];
    const float* f2oW     = (const float*)d_in[10];
    const float* f2ob     = (const float*)d_in[11];
    const float* aW1      = (const float*)d_in[12];
    const float* ab1      = (const float*)d_in[13];
    const float* aW2      = (const float*)d_in[14];
    const float* ab2      = (const float*)d_in[15];
    const float* pW1      = (const float*)d_in[16];
    const float* pb1      = (const float*)d_in[17];
    const float* pW2      = (const float*)d_in[18];
    const float* pb2      = (const float*)d_in[19];
    const float* eW1      = (const float*)d_in[20];
    const float* eb1      = (const float*)d_in[21];
    const float* eW2      = (const float*)d_in[22];
    const float* eb2      = (const float*)d_in[23];
    const int*   neighbors= (const int*)d_in[24];

    float* out = (float*)d_out;
    float* out_vi = out;                          // [B,A,NCB]
    float* out_V  = out + (size_t)BB*AA*NCB;      // [B,A,N,NCB,3]

    cudaFuncSetAttribute(k_main, cudaFuncAttributeMaxDynamicSharedMemorySize,
                         (int)SMEM_BYTES);

    k_init<<<7 + BB*AA/2, 256>>>(fW1, fW2, f2oW, pW1, pW2, eW1, eW2, xi, in2f_W);
    k_main<<<BB*AA/2, 512, SMEM_BYTES>>>(
        r_ij, cos_ij, f_ij, nmask,
        fb1, fb2, f2ob, aW1, ab1, aW2, ab2,
        pb1, pb2, eb1, eb2, neighbors, out_vi);
    k_assemble<<<BB*AA*NN, 96>>>(cos_ij, neighbors, out_V);
}